// round 4
// baseline (speedup 1.0000x reference)
#include <cuda_runtime.h>

// ---------------- problem constants ----------------
#define NCB   9
#define BB    16
#define DD    512
#define TT    4096
#define KK    1024
#define CDIM  8

#define TILE     64
#define THREADS  1024

// output layout (float32, concatenated)
#define ZQ_OFF     0ll
#define CODES_OFF  33554432ll
#define LAT_OFF    34144256ll
#define LOSS_OFF   38862848ll

// ---------------- smem layout (float offsets) ----------------
#define S_R     0          // r[d][p]   512*64 = 32768
#define S_WI    32768      // packed [d][c] 4096 (16B aligned)
#define S_WO    36864      // [c][d] 4096
#define S_CBT   40960      // [c][k] 8*1024 = 8192
#define S_C2    49152      // 1024
#define S_BOUT  50176      // 512
#define S_BIN   50688      // 8
#define S_ZE    50696      // [c][p] 512
#define S_EN    51208      // [c][p] 512
#define S_EN2   51720      // 64
#define S_PART  51784      // 64*65 = 4160 (A partials; reused as BESTD/BESTI in B)
#define S_BESTD S_PART
#define S_BESTI (S_PART+1024)
#define S_CBQ   55944      // [p*9+c] 576
#define S_LOSS  56520      // 64 doubles = 128 floats (8B aligned)
#define SMEM_FLOATS 56648
#define SMEM_BYTES  (SMEM_FLOATS*4)   // 226592

// ---------------- device scratch ----------------
__device__ float  g_wi_p[NCB * DD * CDIM];   // [i][d][c]
__device__ float  g_wo_t[NCB * CDIM * DD];   // [i][c][d]
__device__ float  g_cbt [NCB * CDIM * KK];   // [i][c][k] (normalized, transposed)
__device__ float  g_c2  [NCB * KK];
__device__ double g_loss;

// ---------------- packed f32x2 helpers ----------------
typedef unsigned long long u64;
__device__ __forceinline__ u64 pk2(float lo, float hi) {
    u64 r; asm("mov.b64 %0,{%1,%2};" : "=l"(r) : "f"(lo), "f"(hi)); return r;
}
__device__ __forceinline__ void upk2(float& lo, float& hi, u64 v) {
    asm("mov.b64 {%0,%1},%2;" : "=f"(lo), "=f"(hi) : "l"(v));
}
__device__ __forceinline__ u64 f2fma(u64 a, u64 b, u64 c) {
    u64 d; asm("fma.rn.f32x2 %0,%1,%2,%3;" : "=l"(d) : "l"(a), "l"(b), "l"(c)); return d;
}
__device__ __forceinline__ u64 f2mul(u64 a, u64 b) {
    u64 d; asm("mul.rn.f32x2 %0,%1,%2;" : "=l"(d) : "l"(a), "l"(b)); return d;
}
__device__ __forceinline__ u64 f2add(u64 a, u64 b) {
    u64 d; asm("add.rn.f32x2 %0,%1,%2;" : "=l"(d) : "l"(a), "l"(b)); return d;
}
__device__ __forceinline__ void cp16(unsigned smaddr, const float* g) {
    asm volatile("cp.async.cg.shared.global [%0], [%1], 16;" :: "r"(smaddr), "l"(g));
}
#define CP_COMMIT() asm volatile("cp.async.commit_group;")
#define CP_WAIT(n)  asm volatile("cp.async.wait_group %0;" :: "n"(n))

// ---------------- prep: normalize + transpose, zero loss ----------------
__global__ void rvq_prep(const float* __restrict__ cb,
                         const float* __restrict__ w_in,
                         const float* __restrict__ w_out) {
    int v = blockIdx.x * blockDim.x + threadIdx.x;
    if (v == 0) g_loss = 0.0;
    if (v < NCB * KK) {
        int i = v / KK, k = v % KK;
        const float* src = cb + (size_t)v * CDIM;
        float x[CDIM];
#pragma unroll
        for (int c = 0; c < CDIM; c++) x[c] = src[c];
        float ss = 0.f;
#pragma unroll
        for (int c = 0; c < CDIM; c++) ss = fmaf(x[c], x[c], ss);
        float den = fmaxf(__fsqrt_rn(ss), 1e-12f);
        float c2 = 0.f;
#pragma unroll
        for (int c = 0; c < CDIM; c++) {
            float e = __fdiv_rn(x[c], den);   // exact IEEE div, matches reference
            g_cbt[((size_t)i * CDIM + c) * KK + k] = e;
            c2 = fmaf(e, e, c2);
        }
        g_c2[v] = c2;
    }
    // weight repack: w_in[i][c][d] -> g_wi_p[i][d][c]; w_out[i][d][c] -> g_wo_t[i][c][d]
    for (int idx = v; idx < NCB * DD * CDIM; idx += gridDim.x * blockDim.x) {
        int i = idx / (DD * CDIM), rem = idx % (DD * CDIM);
        int c = rem / DD, d = rem % DD;
        g_wi_p[(size_t)i * DD * CDIM + d * CDIM + c] = w_in[idx];       // idx=[i][c][d]
        int d2 = rem / CDIM, c2i = rem % CDIM;
        g_wo_t[(size_t)i * CDIM * DD + c2i * DD + d2] = w_out[idx];     // idx=[i][d][c]
    }
}

// ---------------- main fused kernel ----------------
extern __shared__ float sm[];

__global__ void __launch_bounds__(THREADS, 1)
rvq_main(const float* __restrict__ z,
         const float* __restrict__ b_in,
         const float* __restrict__ b_out,
         const float* __restrict__ cbraw,
         float* __restrict__ out) {
    const int tid  = threadIdx.x;
    const int pos0 = blockIdx.x * TILE;
    const int b    = pos0 >> 12;
    const int t0   = pos0 & (TT - 1);
    const unsigned smb = (unsigned)__cvta_generic_to_shared(sm);

    const float* zb = z + ((size_t)b * DD) * TT + t0;

    // stage residual r[d][p]
    for (int idx = tid; idx < DD * TILE; idx += THREADS) {
        int d = idx >> 6, p = idx & 63;
        sm[S_R + d * 64 + p] = zb[(size_t)d * TT + p];
    }

    const int p  = tid & 63;
    const int sl = tid >> 6;          // 0..15
    double lossAcc = 0.0;

    for (int i = 0; i < NCB; ++i) {
        __syncthreads();   // prev iter fully done; r staged

        // ---- stage weights via cp.async (3 groups) ----
        if (tid < CDIM) sm[S_BIN + tid] = b_in[(size_t)i * CDIM + tid];
        {
            const float* wi = g_wi_p + (size_t)i * DD * CDIM;
            cp16(smb + (S_WI + tid * 4) * 4, wi + tid * 4);
        }
        CP_COMMIT();   // group: wi
        {
            const float* ct = g_cbt + (size_t)i * CDIM * KK;
            cp16(smb + (S_CBT + tid * 4) * 4,        ct + tid * 4);
            cp16(smb + (S_CBT + 4096 + tid * 4) * 4, ct + 4096 + tid * 4);
            if (tid < 256) cp16(smb + (S_C2 + tid * 4) * 4, g_c2 + (size_t)i * KK + tid * 4);
        }
        CP_COMMIT();   // group: cbt + c2
        {
            const float* wo = g_wo_t + (size_t)i * CDIM * DD;
            cp16(smb + (S_WO + tid * 4) * 4, wo + tid * 4);
            if (tid < 128) cp16(smb + (S_BOUT + tid * 4) * 4, b_out + (size_t)i * DD + tid * 4);
        }
        CP_COMMIT();   // group: wo + bout

        CP_WAIT(2);    // wi ready
        __syncthreads();

        // ---- Phase A: partial z_e over this thread's 32-d chunk (packed) ----
        float v0,v1,v2,v3,v4,v5,v6,v7;
        {
            const int d0 = sl << 5;
            u64 a01 = 0, a23 = 0, a45 = 0, a67 = 0;
            const float* rp = sm + S_R + p;
#pragma unroll 8
            for (int d = d0; d < d0 + 32; ++d) {
                float rv = rp[d * 64];
                u64 rr = pk2(rv, rv);
                ulonglong2 wA = *reinterpret_cast<const ulonglong2*>(sm + S_WI + d * 8);
                ulonglong2 wB = *reinterpret_cast<const ulonglong2*>(sm + S_WI + d * 8 + 4);
                a01 = f2fma(wA.x, rr, a01);
                a23 = f2fma(wA.y, rr, a23);
                a45 = f2fma(wB.x, rr, a45);
                a67 = f2fma(wB.y, rr, a67);
            }
            upk2(v0,v1,a01); upk2(v2,v3,a23); upk2(v4,v5,a45); upk2(v6,v7,a67);
        }
        // stage 1: chunks 8..15 store partials
        if (sl >= 8) {
            float* pb = sm + S_PART + p * 65 + (sl - 8) * 8;
            pb[0]=v0; pb[1]=v1; pb[2]=v2; pb[3]=v3;
            pb[4]=v4; pb[5]=v5; pb[6]=v6; pb[7]=v7;
        }
        __syncthreads();
        // stage 2: chunks 0..7 merge with partner chunk (sl+8)
        if (sl < 8) {
            float* pb = sm + S_PART + p * 65 + sl * 8;
            pb[0]+=v0; pb[1]+=v1; pb[2]+=v2; pb[3]+=v3;
            pb[4]+=v4; pb[5]+=v5; pb[6]+=v6; pb[7]+=v7;
        }
        __syncthreads();

        // ---- combineA: z_e[c][p] = sum of 8 merged partials + b_in[c] ----
        if (tid < 512) {
            int c = tid >> 6, pp = tid & 63;
            const float* pb = sm + S_PART + pp * 65 + c;
            float s = pb[0];
#pragma unroll
            for (int s8 = 1; s8 < 8; s8++) s += pb[s8 * 8];
            sm[S_ZE + c * 64 + pp] = s + sm[S_BIN + c];
        }
        __syncthreads();

        // ---- normalize (tid<64): en, en2 ----
        if (tid < 64) {
            float zv[8];
#pragma unroll
            for (int c = 0; c < 8; c++) zv[c] = sm[S_ZE + c * 64 + tid];
            float ss = 0.f;
#pragma unroll
            for (int c = 0; c < 8; c++) ss = fmaf(zv[c], zv[c], ss);
            float den = fmaxf(__fsqrt_rn(ss), 1e-12f);
            float e[8], en2 = 0.f;
#pragma unroll
            for (int c = 0; c < 8; c++) { e[c] = __fdiv_rn(zv[c], den); sm[S_EN + c * 64 + tid] = e[c]; }
#pragma unroll
            for (int c = 0; c < 8; c++) en2 = fmaf(e[c], e[c], en2);
            sm[S_EN2 + tid] = en2;
        }
        CP_WAIT(1);   // cbt + c2 ready
        __syncthreads();

        // ---- Phase B: argmin over 64 codes in this slice (packed, 4 codes/iter) ----
        {
            u64 ee[8];
#pragma unroll
            for (int c = 0; c < 8; c++) { float e = sm[S_EN + c * 64 + p]; ee[c] = pk2(e, e); }
            float en2 = sm[S_EN2 + p];
            u64 e2s = pk2(en2, en2);
            u64 m2s = pk2(-2.f, -2.f);

            const int k0 = sl << 6;
            float best = 3.402823466e38f;
            int   bi   = k0;
#pragma unroll 8
            for (int q = 0; q < 16; ++q) {
                const int kb = k0 + (q << 2);
                ulonglong2 c0 = *reinterpret_cast<const ulonglong2*>(sm + S_CBT + 0*KK + kb);
                ulonglong2 c1 = *reinterpret_cast<const ulonglong2*>(sm + S_CBT + 1*KK + kb);
                ulonglong2 c2r= *reinterpret_cast<const ulonglong2*>(sm + S_CBT + 2*KK + kb);
                ulonglong2 c3 = *reinterpret_cast<const ulonglong2*>(sm + S_CBT + 3*KK + kb);
                ulonglong2 c4 = *reinterpret_cast<const ulonglong2*>(sm + S_CBT + 4*KK + kb);
                ulonglong2 c5 = *reinterpret_cast<const ulonglong2*>(sm + S_CBT + 5*KK + kb);
                ulonglong2 c6 = *reinterpret_cast<const ulonglong2*>(sm + S_CBT + 6*KK + kb);
                ulonglong2 c7 = *reinterpret_cast<const ulonglong2*>(sm + S_CBT + 7*KK + kb);
                u64 dA = f2mul(ee[0], c0.x);
                dA = f2fma(ee[1], c1.x, dA); dA = f2fma(ee[2], c2r.x, dA);
                dA = f2fma(ee[3], c3.x, dA); dA = f2fma(ee[4], c4.x, dA);
                dA = f2fma(ee[5], c5.x, dA); dA = f2fma(ee[6], c6.x, dA);
                dA = f2fma(ee[7], c7.x, dA);
                u64 dB = f2mul(ee[0], c0.y);
                dB = f2fma(ee[1], c1.y, dB); dB = f2fma(ee[2], c2r.y, dB);
                dB = f2fma(ee[3], c3.y, dB); dB = f2fma(ee[4], c4.y, dB);
                dB = f2fma(ee[5], c5.y, dB); dB = f2fma(ee[6], c6.y, dB);
                dB = f2fma(ee[7], c7.y, dB);
                ulonglong2 c2p = *reinterpret_cast<const ulonglong2*>(sm + S_C2 + kb);
                u64 distA = f2add(f2fma(m2s, dA, e2s), c2p.x);   // (en2-2dot)+c2, per-lane exact
                u64 distB = f2add(f2fma(m2s, dB, e2s), c2p.y);
                float f0,f1,f2,f3;
                upk2(f0,f1,distA); upk2(f2,f3,distB);
                if (f0 < best) { best = f0; bi = kb;     }
                if (f1 < best) { best = f1; bi = kb + 1; }
                if (f2 < best) { best = f2; bi = kb + 2; }
                if (f3 < best) { best = f3; bi = kb + 3; }
            }
            sm[S_BESTD + (sl << 6) + p] = best;
            reinterpret_cast<int*>(sm + S_BESTI)[(sl << 6) + p] = bi;
        }
        __syncthreads();

        // ---- combineB: latents, codes, gather raw codebook, loss ----
        if (tid < 512) {
            int c = tid >> 6, pp = tid & 63;
            out[LAT_OFF + ((size_t)(b * (NCB*CDIM) + i*CDIM + c)) * TT + t0 + pp] =
                sm[S_ZE + c * 64 + pp];
        }
        if (tid < 64) {
            float bestd = sm[S_BESTD + tid];
            int   bi    = reinterpret_cast<int*>(sm + S_BESTI)[tid];
#pragma unroll
            for (int s = 1; s < 16; s++) {      // ascending k ranges: ties keep lowest k
                float d2 = sm[S_BESTD + (s << 6) + tid];
                int   i2 = reinterpret_cast<int*>(sm + S_BESTI)[(s << 6) + tid];
                if (d2 < bestd) { bestd = d2; bi = i2; }
            }
            out[CODES_OFF + ((size_t)(b * NCB + i)) * TT + t0 + tid] = (float)bi;
            const float* cr = cbraw + ((size_t)i * KK + bi) * CDIM;
            double ls = 0.0;
#pragma unroll
            for (int cc = 0; cc < 8; cc++) {
                float cv = __ldg(cr + cc);
                sm[S_CBQ + tid * 9 + cc] = cv;
                float df = sm[S_ZE + cc * 64 + tid] - cv;
                ls += (double)(df * df);
            }
            lossAcc += ls;
        }
        CP_WAIT(0);   // wo + bout ready
        __syncthreads();

        // ---- Phase C: r[d0..d0+32, p] -= w_out @ q[p] + b_out (packed over d) ----
        {
            u64 qq[8];
#pragma unroll
            for (int c = 0; c < 8; c++) { float qv = sm[S_CBQ + p * 9 + c]; qq[c] = pk2(qv, qv); }
            const int d0 = sl << 5;
            float* rp = sm + S_R + p;
#pragma unroll 4
            for (int d = d0; d < d0 + 32; d += 4) {
                ulonglong2 w0 = *reinterpret_cast<const ulonglong2*>(sm + S_WO + 0*DD + d);
                ulonglong2 w1 = *reinterpret_cast<const ulonglong2*>(sm + S_WO + 1*DD + d);
                ulonglong2 w2 = *reinterpret_cast<const ulonglong2*>(sm + S_WO + 2*DD + d);
                ulonglong2 w3 = *reinterpret_cast<const ulonglong2*>(sm + S_WO + 3*DD + d);
                ulonglong2 w4 = *reinterpret_cast<const ulonglong2*>(sm + S_WO + 4*DD + d);
                ulonglong2 w5 = *reinterpret_cast<const ulonglong2*>(sm + S_WO + 5*DD + d);
                ulonglong2 w6 = *reinterpret_cast<const ulonglong2*>(sm + S_WO + 6*DD + d);
                ulonglong2 w7 = *reinterpret_cast<const ulonglong2*>(sm + S_WO + 7*DD + d);
                u64 aA = f2mul(qq[0], w0.x);
                aA = f2fma(qq[1], w1.x, aA); aA = f2fma(qq[2], w2.x, aA);
                aA = f2fma(qq[3], w3.x, aA); aA = f2fma(qq[4], w4.x, aA);
                aA = f2fma(qq[5], w5.x, aA); aA = f2fma(qq[6], w6.x, aA);
                aA = f2fma(qq[7], w7.x, aA);
                u64 aB = f2mul(qq[0], w0.y);
                aB = f2fma(qq[1], w1.y, aB); aB = f2fma(qq[2], w2.y, aB);
                aB = f2fma(qq[3], w3.y, aB); aB = f2fma(qq[4], w4.y, aB);
                aB = f2fma(qq[5], w5.y, aB); aB = f2fma(qq[6], w6.y, aB);
                aB = f2fma(qq[7], w7.y, aB);
                ulonglong2 bo = *reinterpret_cast<const ulonglong2*>(sm + S_BOUT + d);
                aA = f2add(aA, bo.x);
                aB = f2add(aB, bo.y);
                float a0,a1,a2,a3;
                upk2(a0,a1,aA); upk2(a2,a3,aB);
                rp[(d    ) * 64] -= a0;
                rp[(d + 1) * 64] -= a1;
                rp[(d + 2) * 64] -= a2;
                rp[(d + 3) * 64] -= a3;
            }
        }
    }
    __syncthreads();

    // ---- epilogue: z_q = z - r_final ----
    for (int idx = tid; idx < DD * TILE; idx += THREADS) {
        int d = idx >> 6, pp = idx & 63;
        size_t g = ((size_t)(b * DD + d)) * TT + t0 + pp;
        out[ZQ_OFF + g] = z[g] - sm[S_R + d * 64 + pp];
    }

    // ---- loss: deterministic in-block sum, one atomic ----
    double* lb = reinterpret_cast<double*>(sm + S_LOSS);
    if (tid < 64) lb[tid] = lossAcc;
    __syncthreads();
    if (tid == 0) {
        double s = 0.0;
        for (int j = 0; j < 64; j++) s += lb[j];
        atomicAdd(&g_loss, s);
    }
}

__global__ void rvq_fin(float* __restrict__ out) {
    float v = (float)(g_loss * (1.0 / 524288.0));
    out[LOSS_OFF]     = v;
    out[LOSS_OFF + 1] = v;
}

extern "C" void kernel_launch(void* const* d_in, const int* in_sizes, int n_in,
                              void* d_out, int out_size) {
    const float* z     = (const float*)d_in[0];
    const float* w_in  = (const float*)d_in[1];
    const float* b_in  = (const float*)d_in[2];
    const float* w_out = (const float*)d_in[3];
    const float* b_out = (const float*)d_in[4];
    const float* cb    = (const float*)d_in[5];
    float* out = (float*)d_out;

    cudaFuncSetAttribute(rvq_main, cudaFuncAttributeMaxDynamicSharedMemorySize, SMEM_BYTES);

    rvq_prep<<<40, 256>>>(cb, w_in, w_out);
    rvq_main<<<(BB * TT) / TILE, THREADS, SMEM_BYTES>>>(z, b_in, b_out, cb, out);
    rvq_fin<<<1, 1>>>(out);
}

// round 5
// speedup vs baseline: 1.0840x; 1.0840x over previous
#include <cuda_runtime.h>

// ---------------- problem constants ----------------
#define NCB   9
#define BB    16
#define DD    512
#define TT    4096
#define KK    1024
#define CDIM  8

#define TILE     64
#define THREADS  512

// output layout (float32, concatenated)
#define ZQ_OFF     0ll
#define CODES_OFF  33554432ll
#define LAT_OFF    34144256ll
#define LOSS_OFF   38862848ll

// ---------------- smem layout (float offsets) ----------------
#define S_WI    0          // packed [d][c] 4096
#define S_WO    4096       // [c][d] 4096
#define S_CBT   8192       // [c][k] 8192
#define S_C2    16384      // 1024
#define S_BOUT  17408      // 512
#define S_BIN   17920      // 8
#define S_ZE    17928      // [c][p] 512
#define S_EN    18440      // [c][p] 512
#define S_EN2   18952      // 64
#define S_PART  19016      // 64*65 = 4160 (A partials; reused as BESTD/BESTI in B)
#define S_BESTD S_PART
#define S_BESTI (S_PART+512)
#define S_CBQ   23176      // [p*9+c] 576
#define S_LOSS  23752      // 64 doubles = 128 floats (byte 95008, 8-aligned)
#define SMEM_FLOATS 23880
#define SMEM_BYTES  (SMEM_FLOATS*4)   // 95520

// ---------------- device scratch ----------------
__device__ float  g_wi_p[NCB * DD * CDIM];   // [i][d][c]
__device__ float  g_wo_t[NCB * CDIM * DD];   // [i][c][d]
__device__ float  g_cbt [NCB * CDIM * KK];   // [i][c][k] (normalized, transposed)
__device__ float  g_c2  [NCB * KK];
__device__ double g_loss;

// ---------------- packed f32x2 helpers ----------------
typedef unsigned long long u64;
__device__ __forceinline__ u64 pk2(float lo, float hi) {
    u64 r; asm("mov.b64 %0,{%1,%2};" : "=l"(r) : "f"(lo), "f"(hi)); return r;
}
__device__ __forceinline__ void upk2(float& lo, float& hi, u64 v) {
    asm("mov.b64 {%0,%1},%2;" : "=f"(lo), "=f"(hi) : "l"(v));
}
__device__ __forceinline__ u64 f2fma(u64 a, u64 b, u64 c) {
    u64 d; asm("fma.rn.f32x2 %0,%1,%2,%3;" : "=l"(d) : "l"(a), "l"(b), "l"(c)); return d;
}
__device__ __forceinline__ u64 f2mul(u64 a, u64 b) {
    u64 d; asm("mul.rn.f32x2 %0,%1,%2;" : "=l"(d) : "l"(a), "l"(b)); return d;
}
__device__ __forceinline__ u64 f2add(u64 a, u64 b) {
    u64 d; asm("add.rn.f32x2 %0,%1,%2;" : "=l"(d) : "l"(a), "l"(b)); return d;
}
__device__ __forceinline__ void cp16(unsigned smaddr, const float* g) {
    asm volatile("cp.async.cg.shared.global [%0], [%1], 16;" :: "r"(smaddr), "l"(g));
}
#define CP_COMMIT() asm volatile("cp.async.commit_group;")
#define CP_WAIT(n)  asm volatile("cp.async.wait_group %0;" :: "n"(n))

// ---------------- prep: normalize + transpose, zero loss ----------------
__global__ void rvq_prep(const float* __restrict__ cb,
                         const float* __restrict__ w_in,
                         const float* __restrict__ w_out) {
    int v = blockIdx.x * blockDim.x + threadIdx.x;
    if (v == 0) g_loss = 0.0;
    if (v < NCB * KK) {
        int i = v / KK, k = v % KK;
        const float* src = cb + (size_t)v * CDIM;
        float x[CDIM];
#pragma unroll
        for (int c = 0; c < CDIM; c++) x[c] = src[c];
        float ss = 0.f;
#pragma unroll
        for (int c = 0; c < CDIM; c++) ss = fmaf(x[c], x[c], ss);
        float den = fmaxf(__fsqrt_rn(ss), 1e-12f);
        float c2 = 0.f;
#pragma unroll
        for (int c = 0; c < CDIM; c++) {
            float e = __fdiv_rn(x[c], den);   // exact IEEE div, matches reference
            g_cbt[((size_t)i * CDIM + c) * KK + k] = e;
            c2 = fmaf(e, e, c2);
        }
        g_c2[v] = c2;
    }
    for (int idx = v; idx < NCB * DD * CDIM; idx += gridDim.x * blockDim.x) {
        int i = idx / (DD * CDIM), rem = idx % (DD * CDIM);
        int c = rem / DD, d = rem % DD;
        g_wi_p[(size_t)i * DD * CDIM + d * CDIM + c] = w_in[idx];       // idx=[i][c][d]
        int d2 = rem / CDIM, c2i = rem % CDIM;
        g_wo_t[(size_t)i * CDIM * DD + c2i * DD + d2] = w_out[idx];     // idx=[i][d][c]
    }
}

// ---------------- main fused kernel ----------------
extern __shared__ float sm[];

__global__ void __launch_bounds__(THREADS, 1)
rvq_main(const float* __restrict__ z,
         const float* __restrict__ b_in,
         const float* __restrict__ b_out,
         const float* __restrict__ cbraw,
         float* __restrict__ out) {
    const int tid  = threadIdx.x;
    const int pos0 = blockIdx.x * TILE;
    const int b    = pos0 >> 12;
    const int t0   = pos0 & (TT - 1);
    const unsigned smb = (unsigned)__cvta_generic_to_shared(sm);

    const int p  = tid & 63;
    const int sl = tid >> 6;          // 0..7
    const int d0 = sl << 6;           // this thread's 64-d chunk

    // residual lives in REGISTERS: r[dd] = residual[d0+dd][p]
    const float* zc = z + ((size_t)b * DD + d0) * TT + t0 + p;
    float r[64];
#pragma unroll
    for (int dd = 0; dd < 64; dd++) r[dd] = zc[(size_t)dd * TT];

    double lossAcc = 0.0;

    for (int i = 0; i < NCB; ++i) {
        __syncthreads();   // prev iter's C (reads WO/CBQ) done before restage

        // ---- stage weights via cp.async (3 groups) ----
        if (tid < CDIM) sm[S_BIN + tid] = b_in[(size_t)i * CDIM + tid];
        {
            const float* wi = g_wi_p + (size_t)i * DD * CDIM;
            cp16(smb + (S_WI + tid * 4) * 4,        wi + tid * 4);
            cp16(smb + (S_WI + 2048 + tid * 4) * 4, wi + 2048 + tid * 4);
        }
        CP_COMMIT();   // group: wi
        {
            const float* ct = g_cbt + (size_t)i * CDIM * KK;
#pragma unroll
            for (int r4 = 0; r4 < 4; r4++)
                cp16(smb + (S_CBT + r4 * 2048 + tid * 4) * 4, ct + r4 * 2048 + tid * 4);
            if (tid < 256) cp16(smb + (S_C2 + tid * 4) * 4, g_c2 + (size_t)i * KK + tid * 4);
        }
        CP_COMMIT();   // group: cbt + c2
        {
            const float* wo = g_wo_t + (size_t)i * CDIM * DD;
            cp16(smb + (S_WO + tid * 4) * 4,        wo + tid * 4);
            cp16(smb + (S_WO + 2048 + tid * 4) * 4, wo + 2048 + tid * 4);
            if (tid < 128) cp16(smb + (S_BOUT + tid * 4) * 4, b_out + (size_t)i * DD + tid * 4);
        }
        CP_COMMIT();   // group: wo + bout

        CP_WAIT(2);    // wi ready
        __syncthreads();

        // ---- Phase A: partial z_e over this thread's 64-d register chunk ----
        {
            u64 a01 = 0, a23 = 0, a45 = 0, a67 = 0;
#pragma unroll
            for (int dd = 0; dd < 64; dd++) {
                float rv = r[dd];
                u64 rr = pk2(rv, rv);
                ulonglong2 wA = *reinterpret_cast<const ulonglong2*>(sm + S_WI + (d0 + dd) * 8);
                ulonglong2 wB = *reinterpret_cast<const ulonglong2*>(sm + S_WI + (d0 + dd) * 8 + 4);
                a01 = f2fma(wA.x, rr, a01);
                a23 = f2fma(wA.y, rr, a23);
                a45 = f2fma(wB.x, rr, a45);
                a67 = f2fma(wB.y, rr, a67);
            }
            float v0,v1,v2,v3,v4,v5,v6,v7;
            upk2(v0,v1,a01); upk2(v2,v3,a23); upk2(v4,v5,a45); upk2(v6,v7,a67);
            // PART element (p, sl, c) at p*65 + c*8 + sl
            float* pb = sm + S_PART + p * 65 + sl;
            pb[0]=v0; pb[8]=v1; pb[16]=v2; pb[24]=v3;
            pb[32]=v4; pb[40]=v5; pb[48]=v6; pb[56]=v7;
        }
        __syncthreads();

        // ---- combineA + normalize (tid<64): z_e, en, en2 ----
        if (tid < 64) {
            float zv[8];
#pragma unroll
            for (int c = 0; c < 8; c++) {
                const float* pb = sm + S_PART + tid * 65 + c * 8;
                float s = pb[0];
#pragma unroll
                for (int s8 = 1; s8 < 8; s8++) s += pb[s8];
                zv[c] = s + sm[S_BIN + c];
                sm[S_ZE + c * 64 + tid] = zv[c];
            }
            float ss = 0.f;
#pragma unroll
            for (int c = 0; c < 8; c++) ss = fmaf(zv[c], zv[c], ss);
            float den = fmaxf(__fsqrt_rn(ss), 1e-12f);
            float e[8], en2 = 0.f;
#pragma unroll
            for (int c = 0; c < 8; c++) { e[c] = __fdiv_rn(zv[c], den); sm[S_EN + c * 64 + tid] = e[c]; }
#pragma unroll
            for (int c = 0; c < 8; c++) en2 = fmaf(e[c], e[c], en2);
            sm[S_EN2 + tid] = en2;
        }
        CP_WAIT(1);   // cbt + c2 ready
        __syncthreads();

        // ---- Phase B: argmin over 128 codes in this slice (packed, 4 codes/iter) ----
        {
            u64 ee[8];
#pragma unroll
            for (int c = 0; c < 8; c++) { float e = sm[S_EN + c * 64 + p]; ee[c] = pk2(e, e); }
            float en2 = sm[S_EN2 + p];
            u64 e2s = pk2(en2, en2);
            u64 m2s = pk2(-2.f, -2.f);

            const int k0 = sl << 7;
            float best = 3.402823466e38f;
            int   bi   = k0;
#pragma unroll 8
            for (int q = 0; q < 32; ++q) {
                const int kb = k0 + (q << 2);
                ulonglong2 c0 = *reinterpret_cast<const ulonglong2*>(sm + S_CBT + 0*KK + kb);
                ulonglong2 c1 = *reinterpret_cast<const ulonglong2*>(sm + S_CBT + 1*KK + kb);
                ulonglong2 c2r= *reinterpret_cast<const ulonglong2*>(sm + S_CBT + 2*KK + kb);
                ulonglong2 c3 = *reinterpret_cast<const ulonglong2*>(sm + S_CBT + 3*KK + kb);
                ulonglong2 c4 = *reinterpret_cast<const ulonglong2*>(sm + S_CBT + 4*KK + kb);
                ulonglong2 c5 = *reinterpret_cast<const ulonglong2*>(sm + S_CBT + 5*KK + kb);
                ulonglong2 c6 = *reinterpret_cast<const ulonglong2*>(sm + S_CBT + 6*KK + kb);
                ulonglong2 c7 = *reinterpret_cast<const ulonglong2*>(sm + S_CBT + 7*KK + kb);
                u64 dA = f2mul(ee[0], c0.x);
                dA = f2fma(ee[1], c1.x, dA); dA = f2fma(ee[2], c2r.x, dA);
                dA = f2fma(ee[3], c3.x, dA); dA = f2fma(ee[4], c4.x, dA);
                dA = f2fma(ee[5], c5.x, dA); dA = f2fma(ee[6], c6.x, dA);
                dA = f2fma(ee[7], c7.x, dA);
                u64 dB = f2mul(ee[0], c0.y);
                dB = f2fma(ee[1], c1.y, dB); dB = f2fma(ee[2], c2r.y, dB);
                dB = f2fma(ee[3], c3.y, dB); dB = f2fma(ee[4], c4.y, dB);
                dB = f2fma(ee[5], c5.y, dB); dB = f2fma(ee[6], c6.y, dB);
                dB = f2fma(ee[7], c7.y, dB);
                ulonglong2 c2p = *reinterpret_cast<const ulonglong2*>(sm + S_C2 + kb);
                u64 distA = f2add(f2fma(m2s, dA, e2s), c2p.x);   // (en2-2dot)+c2, per-lane exact
                u64 distB = f2add(f2fma(m2s, dB, e2s), c2p.y);
                float f0,f1,f2,f3;
                upk2(f0,f1,distA); upk2(f2,f3,distB);
                if (f0 < best) { best = f0; bi = kb;     }
                if (f1 < best) { best = f1; bi = kb + 1; }
                if (f2 < best) { best = f2; bi = kb + 2; }
                if (f3 < best) { best = f3; bi = kb + 3; }
            }
            sm[S_BESTD + (sl << 6) + p] = best;
            reinterpret_cast<int*>(sm + S_BESTI)[(sl << 6) + p] = bi;
        }
        __syncthreads();

        // ---- combineB: latents, codes, gather raw codebook, loss ----
        out[LAT_OFF + ((size_t)(b * (NCB*CDIM) + i*CDIM + sl)) * TT + t0 + p] =
            sm[S_ZE + sl * 64 + p];
        if (tid < 64) {
            float bestd = sm[S_BESTD + tid];
            int   bi    = reinterpret_cast<int*>(sm + S_BESTI)[tid];
#pragma unroll
            for (int s = 1; s < 8; s++) {     // ascending k ranges: ties keep lowest k
                float d2 = sm[S_BESTD + (s << 6) + tid];
                int   i2 = reinterpret_cast<int*>(sm + S_BESTI)[(s << 6) + tid];
                if (d2 < bestd) { bestd = d2; bi = i2; }
            }
            out[CODES_OFF + ((size_t)(b * NCB + i)) * TT + t0 + tid] = (float)bi;
            const float* cr = cbraw + ((size_t)i * KK + bi) * CDIM;
            double ls = 0.0;
#pragma unroll
            for (int cc = 0; cc < 8; cc++) {
                float cv = __ldg(cr + cc);
                sm[S_CBQ + tid * 9 + cc] = cv;
                float df = sm[S_ZE + cc * 64 + tid] - cv;
                ls += (double)(df * df);
            }
            lossAcc += ls;
        }
        CP_WAIT(0);   // wo + bout ready
        __syncthreads();

        // ---- Phase C: r[dd] -= w_out[:, d0+dd] . q[p] + b_out  (r in regs) ----
        {
            u64 qq[8];
#pragma unroll
            for (int c = 0; c < 8; c++) { float qv = sm[S_CBQ + p * 9 + c]; qq[c] = pk2(qv, qv); }
#pragma unroll
            for (int dg = 0; dg < 16; dg++) {
                const int d = d0 + dg * 4;
                ulonglong2 w0 = *reinterpret_cast<const ulonglong2*>(sm + S_WO + 0*DD + d);
                ulonglong2 w1 = *reinterpret_cast<const ulonglong2*>(sm + S_WO + 1*DD + d);
                ulonglong2 w2 = *reinterpret_cast<const ulonglong2*>(sm + S_WO + 2*DD + d);
                ulonglong2 w3 = *reinterpret_cast<const ulonglong2*>(sm + S_WO + 3*DD + d);
                ulonglong2 w4 = *reinterpret_cast<const ulonglong2*>(sm + S_WO + 4*DD + d);
                ulonglong2 w5 = *reinterpret_cast<const ulonglong2*>(sm + S_WO + 5*DD + d);
                ulonglong2 w6 = *reinterpret_cast<const ulonglong2*>(sm + S_WO + 6*DD + d);
                ulonglong2 w7 = *reinterpret_cast<const ulonglong2*>(sm + S_WO + 7*DD + d);
                u64 aA = f2mul(qq[0], w0.x);
                aA = f2fma(qq[1], w1.x, aA); aA = f2fma(qq[2], w2.x, aA);
                aA = f2fma(qq[3], w3.x, aA); aA = f2fma(qq[4], w4.x, aA);
                aA = f2fma(qq[5], w5.x, aA); aA = f2fma(qq[6], w6.x, aA);
                aA = f2fma(qq[7], w7.x, aA);
                u64 aB = f2mul(qq[0], w0.y);
                aB = f2fma(qq[1], w1.y, aB); aB = f2fma(qq[2], w2.y, aB);
                aB = f2fma(qq[3], w3.y, aB); aB = f2fma(qq[4], w4.y, aB);
                aB = f2fma(qq[5], w5.y, aB); aB = f2fma(qq[6], w6.y, aB);
                aB = f2fma(qq[7], w7.y, aB);
                ulonglong2 bo = *reinterpret_cast<const ulonglong2*>(sm + S_BOUT + d);
                aA = f2add(aA, bo.x);
                aB = f2add(aB, bo.y);
                float a0,a1,a2,a3;
                upk2(a0,a1,aA); upk2(a2,a3,aB);
                r[dg*4    ] -= a0;
                r[dg*4 + 1] -= a1;
                r[dg*4 + 2] -= a2;
                r[dg*4 + 3] -= a3;
            }
        }
    }

    // ---- epilogue: z_q = z - r_final (r in regs, coalesced global) ----
    {
        float* oq = out + ZQ_OFF + ((size_t)(b * DD + d0)) * TT + t0 + p;
#pragma unroll
        for (int dd = 0; dd < 64; dd++)
            oq[(size_t)dd * TT] = zc[(size_t)dd * TT] - r[dd];
    }

    // ---- loss: deterministic in-block sum, one atomic ----
    __syncthreads();
    double* lb = reinterpret_cast<double*>(sm + S_LOSS);
    if (tid < 64) lb[tid] = lossAcc;
    __syncthreads();
    if (tid == 0) {
        double s = 0.0;
        for (int j = 0; j < 64; j++) s += lb[j];
        atomicAdd(&g_loss, s);
    }
}

__global__ void rvq_fin(float* __restrict__ out) {
    float v = (float)(g_loss * (1.0 / 524288.0));
    out[LOSS_OFF]     = v;
    out[LOSS_OFF + 1] = v;
}

extern "C" void kernel_launch(void* const* d_in, const int* in_sizes, int n_in,
                              void* d_out, int out_size) {
    const float* z     = (const float*)d_in[0];
    const float* w_in  = (const float*)d_in[1];
    const float* b_in  = (const float*)d_in[2];
    const float* w_out = (const float*)d_in[3];
    const float* b_out = (const float*)d_in[4];
    const float* cb    = (const float*)d_in[5];
    float* out = (float*)d_out;

    cudaFuncSetAttribute(rvq_main, cudaFuncAttributeMaxDynamicSharedMemorySize, SMEM_BYTES);

    rvq_prep<<<40, 256>>>(cb, w_in, w_out);
    rvq_main<<<(BB * TT) / TILE, THREADS, SMEM_BYTES>>>(z, b_in, b_out, cb, out);
    rvq_fin<<<1, 1>>>(out);
}

// round 6
// speedup vs baseline: 1.0991x; 1.0140x over previous
#include <cuda_runtime.h>

// ---------------- problem constants ----------------
#define NCB   9
#define BB    16
#define DD    512
#define TT    4096
#define KK    1024
#define CDIM  8

#define TILE     32
#define THREADS  256
#define NCTAS    ((BB * TT) / TILE)     // 2048

// output layout (float32, concatenated)
#define ZQ_OFF     0ll
#define CODES_OFF  33554432ll
#define LAT_OFF    34144256ll
#define LOSS_OFF   38862848ll

// ---------------- smem layout (float offsets) ----------------
#define S_WI    0          // packed [d][c] 4096
#define S_WO    4096       // [c][d] 4096
#define S_CBT   8192       // [c][k] 8192
#define S_C2    16384      // 1024
#define S_BOUT  17408      // 512
#define S_BIN   17920      // 8
#define S_ZE    17928      // [c][p] 8*32 = 256
#define S_PART  18184      // 32*65 = 2080 (A partials; reused as BESTD/BESTI in B)
#define S_BESTD S_PART
#define S_BESTI (S_PART+256)
#define S_CBQ   20264      // [p*9+c] 288
#define S_LOSS  20552      // 32 doubles = 64 floats (byte 82208, 8-aligned)
#define SMEM_FLOATS 20616
#define SMEM_BYTES  (SMEM_FLOATS*4)   // 82464  (x2 CTAs = 164928 < 228KB)

// ---------------- device scratch ----------------
__device__ float    g_wi_p[NCB * DD * CDIM];   // [i][d][c]
__device__ float    g_wo_t[NCB * CDIM * DD];   // [i][c][d]
__device__ float    g_cbt [NCB * CDIM * KK];   // [i][c][k] (normalized, transposed)
__device__ float    g_c2  [NCB * KK];
__device__ double   g_loss;
__device__ unsigned g_done;

// ---------------- packed f32x2 helpers ----------------
typedef unsigned long long u64;
__device__ __forceinline__ u64 pk2(float lo, float hi) {
    u64 r; asm("mov.b64 %0,{%1,%2};" : "=l"(r) : "f"(lo), "f"(hi)); return r;
}
__device__ __forceinline__ void upk2(float& lo, float& hi, u64 v) {
    asm("mov.b64 {%0,%1},%2;" : "=f"(lo), "=f"(hi) : "l"(v));
}
__device__ __forceinline__ u64 f2fma(u64 a, u64 b, u64 c) {
    u64 d; asm("fma.rn.f32x2 %0,%1,%2,%3;" : "=l"(d) : "l"(a), "l"(b), "l"(c)); return d;
}
__device__ __forceinline__ u64 f2mul(u64 a, u64 b) {
    u64 d; asm("mul.rn.f32x2 %0,%1,%2;" : "=l"(d) : "l"(a), "l"(b)); return d;
}
__device__ __forceinline__ u64 f2add(u64 a, u64 b) {
    u64 d; asm("add.rn.f32x2 %0,%1,%2;" : "=l"(d) : "l"(a), "l"(b)); return d;
}
__device__ __forceinline__ void cp16(unsigned smaddr, const float* g) {
    asm volatile("cp.async.cg.shared.global [%0], [%1], 16;" :: "r"(smaddr), "l"(g));
}
#define CP_COMMIT() asm volatile("cp.async.commit_group;")
#define CP_WAIT(n)  asm volatile("cp.async.wait_group %0;" :: "n"(n))

// ---------------- prep: normalize + transpose, zero loss ----------------
__global__ void rvq_prep(const float* __restrict__ cb,
                         const float* __restrict__ w_in,
                         const float* __restrict__ w_out) {
    int v = blockIdx.x * blockDim.x + threadIdx.x;
    if (v == 0) { g_loss = 0.0; g_done = 0u; }
    if (v < NCB * KK) {
        int i = v / KK, k = v % KK;
        const float* src = cb + (size_t)v * CDIM;
        float x[CDIM];
#pragma unroll
        for (int c = 0; c < CDIM; c++) x[c] = src[c];
        float ss = 0.f;
#pragma unroll
        for (int c = 0; c < CDIM; c++) ss = fmaf(x[c], x[c], ss);
        float den = fmaxf(__fsqrt_rn(ss), 1e-12f);
        float c2 = 0.f;
#pragma unroll
        for (int c = 0; c < CDIM; c++) {
            float e = __fdiv_rn(x[c], den);   // exact IEEE div, matches reference
            g_cbt[((size_t)i * CDIM + c) * KK + k] = e;
            c2 = fmaf(e, e, c2);
        }
        g_c2[v] = c2;
    }
    for (int idx = v; idx < NCB * DD * CDIM; idx += gridDim.x * blockDim.x) {
        int i = idx / (DD * CDIM), rem = idx % (DD * CDIM);
        int c = rem / DD, d = rem % DD;
        g_wi_p[(size_t)i * DD * CDIM + d * CDIM + c] = w_in[idx];       // idx=[i][c][d]
        int d2 = rem / CDIM, c2i = rem % CDIM;
        g_wo_t[(size_t)i * CDIM * DD + c2i * DD + d2] = w_out[idx];     // idx=[i][d][c]
    }
}

// ---------------- main fused kernel ----------------
extern __shared__ float sm[];

__global__ void __launch_bounds__(THREADS, 2)
rvq_main(const float* __restrict__ z,
         const float* __restrict__ b_in,
         const float* __restrict__ b_out,
         const float* __restrict__ cbraw,
         float* __restrict__ out) {
    const int tid  = threadIdx.x;
    const int pos0 = blockIdx.x * TILE;
    const int b    = pos0 >> 12;
    const int t0   = pos0 & (TT - 1);
    const unsigned smb = (unsigned)__cvta_generic_to_shared(sm);

    const int p  = tid & 31;          // position within tile
    const int sl = tid >> 5;          // 0..7 (d-chunk for A/C, k-slice for B)
    const int d0 = sl << 6;

    // residual lives in REGISTERS: r[dd] = residual[d0+dd][p]
    const float* zc = z + ((size_t)b * DD + d0) * TT + t0 + p;
    float r[64];
#pragma unroll
    for (int dd = 0; dd < 64; dd++) r[dd] = zc[(size_t)dd * TT];

    double lossAcc = 0.0;

    for (int i = 0; i < NCB; ++i) {
        __syncthreads();   // prev iter's C (reads WO/CBQ) done before restage

        // ---- stage weights via cp.async (3 groups) ----
        if (tid < CDIM) sm[S_BIN + tid] = b_in[(size_t)i * CDIM + tid];
        {
            const float* wi = g_wi_p + (size_t)i * DD * CDIM;
#pragma unroll
            for (int j = 0; j < 4; j++)
                cp16(smb + (S_WI + j * 1024 + tid * 4) * 4, wi + j * 1024 + tid * 4);
        }
        CP_COMMIT();   // group: wi
        {
            const float* ct = g_cbt + (size_t)i * CDIM * KK;
#pragma unroll
            for (int j = 0; j < 8; j++)
                cp16(smb + (S_CBT + j * 1024 + tid * 4) * 4, ct + j * 1024 + tid * 4);
            cp16(smb + (S_C2 + tid * 4) * 4, g_c2 + (size_t)i * KK + tid * 4);
        }
        CP_COMMIT();   // group: cbt + c2
        {
            const float* wo = g_wo_t + (size_t)i * CDIM * DD;
#pragma unroll
            for (int j = 0; j < 4; j++)
                cp16(smb + (S_WO + j * 1024 + tid * 4) * 4, wo + j * 1024 + tid * 4);
            if (tid < 128) cp16(smb + (S_BOUT + tid * 4) * 4, b_out + (size_t)i * DD + tid * 4);
        }
        CP_COMMIT();   // group: wo + bout

        CP_WAIT(2);    // wi ready
        __syncthreads();

        // ---- Phase A: partial z_e over this thread's 64-d register chunk ----
        {
            u64 a01 = 0, a23 = 0, a45 = 0, a67 = 0;
#pragma unroll
            for (int dd = 0; dd < 64; dd++) {
                float rv = r[dd];
                u64 rr = pk2(rv, rv);
                ulonglong2 wA = *reinterpret_cast<const ulonglong2*>(sm + S_WI + (d0 + dd) * 8);
                ulonglong2 wB = *reinterpret_cast<const ulonglong2*>(sm + S_WI + (d0 + dd) * 8 + 4);
                a01 = f2fma(wA.x, rr, a01);
                a23 = f2fma(wA.y, rr, a23);
                a45 = f2fma(wB.x, rr, a45);
                a67 = f2fma(wB.y, rr, a67);
            }
            float v0,v1,v2,v3,v4,v5,v6,v7;
            upk2(v0,v1,a01); upk2(v2,v3,a23); upk2(v4,v5,a45); upk2(v6,v7,a67);
            // PART element (p, c, sl) at p*65 + c*8 + sl
            float* pb = sm + S_PART + p * 65 + sl;
            pb[0]=v0; pb[8]=v1; pb[16]=v2; pb[24]=v3;
            pb[32]=v4; pb[40]=v5; pb[48]=v6; pb[56]=v7;
        }
        __syncthreads();

        // ---- combineA (tid<32): z_e[c][p] ----
        if (tid < 32) {
#pragma unroll
            for (int c = 0; c < 8; c++) {
                const float* pb = sm + S_PART + tid * 65 + c * 8;
                float s = pb[0];
#pragma unroll
                for (int s8 = 1; s8 < 8; s8++) s += pb[s8];
                sm[S_ZE + c * 32 + tid] = s + sm[S_BIN + c];
            }
        }
        CP_WAIT(1);   // cbt + c2 ready
        __syncthreads();

        // ---- Phase B: normalize locally + argmin over 128 codes (4 indep chains) ----
        {
            float zv[8];
#pragma unroll
            for (int c = 0; c < 8; c++) zv[c] = sm[S_ZE + c * 32 + p];
            float ss = 0.f;
#pragma unroll
            for (int c = 0; c < 8; c++) ss = fmaf(zv[c], zv[c], ss);
            float den = fmaxf(__fsqrt_rn(ss), 1e-12f);
            float e[8], en2 = 0.f;
#pragma unroll
            for (int c = 0; c < 8; c++) e[c] = __fdiv_rn(zv[c], den);
#pragma unroll
            for (int c = 0; c < 8; c++) en2 = fmaf(e[c], e[c], en2);

            u64 ee[8];
#pragma unroll
            for (int c = 0; c < 8; c++) ee[c] = pk2(e[c], e[c]);
            u64 e2s = pk2(en2, en2);
            u64 m2s = pk2(-2.f, -2.f);

            const int k0 = sl << 7;
            // 4 independent argmin chains (one per candidate lane)
            float b0 = 3.402823466e38f, b1 = b0, b2 = b0, b3 = b0;
            int   i0 = k0, i1 = k0 + 1, i2 = k0 + 2, i3 = k0 + 3;
#pragma unroll 8
            for (int q = 0; q < 32; ++q) {
                const int kb = k0 + (q << 2);
                ulonglong2 c0 = *reinterpret_cast<const ulonglong2*>(sm + S_CBT + 0*KK + kb);
                ulonglong2 c1 = *reinterpret_cast<const ulonglong2*>(sm + S_CBT + 1*KK + kb);
                ulonglong2 c2r= *reinterpret_cast<const ulonglong2*>(sm + S_CBT + 2*KK + kb);
                ulonglong2 c3 = *reinterpret_cast<const ulonglong2*>(sm + S_CBT + 3*KK + kb);
                ulonglong2 c4 = *reinterpret_cast<const ulonglong2*>(sm + S_CBT + 4*KK + kb);
                ulonglong2 c5 = *reinterpret_cast<const ulonglong2*>(sm + S_CBT + 5*KK + kb);
                ulonglong2 c6 = *reinterpret_cast<const ulonglong2*>(sm + S_CBT + 6*KK + kb);
                ulonglong2 c7 = *reinterpret_cast<const ulonglong2*>(sm + S_CBT + 7*KK + kb);
                u64 dA = f2mul(ee[0], c0.x);
                dA = f2fma(ee[1], c1.x, dA); dA = f2fma(ee[2], c2r.x, dA);
                dA = f2fma(ee[3], c3.x, dA); dA = f2fma(ee[4], c4.x, dA);
                dA = f2fma(ee[5], c5.x, dA); dA = f2fma(ee[6], c6.x, dA);
                dA = f2fma(ee[7], c7.x, dA);
                u64 dB = f2mul(ee[0], c0.y);
                dB = f2fma(ee[1], c1.y, dB); dB = f2fma(ee[2], c2r.y, dB);
                dB = f2fma(ee[3], c3.y, dB); dB = f2fma(ee[4], c4.y, dB);
                dB = f2fma(ee[5], c5.y, dB); dB = f2fma(ee[6], c6.y, dB);
                dB = f2fma(ee[7], c7.y, dB);
                ulonglong2 c2p = *reinterpret_cast<const ulonglong2*>(sm + S_C2 + kb);
                u64 distA = f2add(f2fma(m2s, dA, e2s), c2p.x);   // (en2-2dot)+c2, per-lane exact
                u64 distB = f2add(f2fma(m2s, dB, e2s), c2p.y);
                float f0,f1,f2,f3;
                upk2(f0,f1,distA); upk2(f2,f3,distB);
                if (f0 < b0) { b0 = f0; i0 = kb;     }   // strict <: chain keeps lowest q
                if (f1 < b1) { b1 = f1; i1 = kb + 1; }
                if (f2 < b2) { b2 = f2; i2 = kb + 2; }
                if (f3 < b3) { b3 = f3; i3 = kb + 3; }
            }
            // merge chains with exact lowest-index tie-break
            float best = b0; int bi = i0;
            if (b1 < best || (b1 == best && i1 < bi)) { best = b1; bi = i1; }
            if (b2 < best || (b2 == best && i2 < bi)) { best = b2; bi = i2; }
            if (b3 < best || (b3 == best && i3 < bi)) { best = b3; bi = i3; }
            sm[S_BESTD + (sl << 5) + p] = best;
            reinterpret_cast<int*>(sm + S_BESTI)[(sl << 5) + p] = bi;
        }
        __syncthreads();

        // ---- combineB: latents, codes, gather raw codebook, loss ----
        out[LAT_OFF + ((size_t)(b * (NCB*CDIM) + i*CDIM + sl)) * TT + t0 + p] =
            sm[S_ZE + sl * 32 + p];
        if (tid < 32) {
            float bestd = sm[S_BESTD + tid];
            int   bi    = reinterpret_cast<int*>(sm + S_BESTI)[tid];
#pragma unroll
            for (int s = 1; s < 8; s++) {     // ascending k ranges: strict < keeps lowest k
                float d2 = sm[S_BESTD + (s << 5) + tid];
                int   i2 = reinterpret_cast<int*>(sm + S_BESTI)[(s << 5) + tid];
                if (d2 < bestd) { bestd = d2; bi = i2; }
            }
            out[CODES_OFF + ((size_t)(b * NCB + i)) * TT + t0 + tid] = (float)bi;
            const float* cr = cbraw + ((size_t)i * KK + bi) * CDIM;
            double ls = 0.0;
#pragma unroll
            for (int cc = 0; cc < 8; cc++) {
                float cv = __ldg(cr + cc);
                sm[S_CBQ + tid * 9 + cc] = cv;
                float df = sm[S_ZE + cc * 32 + tid] - cv;
                ls += (double)(df * df);
            }
            lossAcc += ls;
        }
        CP_WAIT(0);   // wo + bout ready
        __syncthreads();

        // ---- Phase C: r[dd] -= w_out[:, d0+dd] . q[p] + b_out  (r in regs) ----
        {
            u64 qq[8];
#pragma unroll
            for (int c = 0; c < 8; c++) { float qv = sm[S_CBQ + p * 9 + c]; qq[c] = pk2(qv, qv); }
#pragma unroll
            for (int dg = 0; dg < 16; dg++) {
                const int d = d0 + dg * 4;
                ulonglong2 w0 = *reinterpret_cast<const ulonglong2*>(sm + S_WO + 0*DD + d);
                ulonglong2 w1 = *reinterpret_cast<const ulonglong2*>(sm + S_WO + 1*DD + d);
                ulonglong2 w2 = *reinterpret_cast<const ulonglong2*>(sm + S_WO + 2*DD + d);
                ulonglong2 w3 = *reinterpret_cast<const ulonglong2*>(sm + S_WO + 3*DD + d);
                ulonglong2 w4 = *reinterpret_cast<const ulonglong2*>(sm + S_WO + 4*DD + d);
                ulonglong2 w5 = *reinterpret_cast<const ulonglong2*>(sm + S_WO + 5*DD + d);
                ulonglong2 w6 = *reinterpret_cast<const ulonglong2*>(sm + S_WO + 6*DD + d);
                ulonglong2 w7 = *reinterpret_cast<const ulonglong2*>(sm + S_WO + 7*DD + d);
                u64 aA = f2mul(qq[0], w0.x);
                aA = f2fma(qq[1], w1.x, aA); aA = f2fma(qq[2], w2.x, aA);
                aA = f2fma(qq[3], w3.x, aA); aA = f2fma(qq[4], w4.x, aA);
                aA = f2fma(qq[5], w5.x, aA); aA = f2fma(qq[6], w6.x, aA);
                aA = f2fma(qq[7], w7.x, aA);
                u64 aB = f2mul(qq[0], w0.y);
                aB = f2fma(qq[1], w1.y, aB); aB = f2fma(qq[2], w2.y, aB);
                aB = f2fma(qq[3], w3.y, aB); aB = f2fma(qq[4], w4.y, aB);
                aB = f2fma(qq[5], w5.y, aB); aB = f2fma(qq[6], w6.y, aB);
                aB = f2fma(qq[7], w7.y, aB);
                ulonglong2 bo = *reinterpret_cast<const ulonglong2*>(sm + S_BOUT + d);
                aA = f2add(aA, bo.x);
                aB = f2add(aB, bo.y);
                float a0,a1,a2,a3;
                upk2(a0,a1,aA); upk2(a2,a3,aB);
                r[dg*4    ] -= a0;
                r[dg*4 + 1] -= a1;
                r[dg*4 + 2] -= a2;
                r[dg*4 + 3] -= a3;
            }
        }
    }

    // ---- epilogue: z_q = z - r_final (r in regs, coalesced global) ----
    {
        float* oq = out + ZQ_OFF + ((size_t)(b * DD + d0)) * TT + t0 + p;
#pragma unroll
        for (int dd = 0; dd < 64; dd++)
            oq[(size_t)dd * TT] = zc[(size_t)dd * TT] - r[dd];
    }

    // ---- loss: deterministic in-block sum, one atomic; last CTA writes scalars ----
    __syncthreads();
    double* lb = reinterpret_cast<double*>(sm + S_LOSS);
    if (tid < 32) lb[tid] = lossAcc;
    __syncthreads();
    if (tid == 0) {
        double s = 0.0;
        for (int j = 0; j < 32; j++) s += lb[j];
        atomicAdd(&g_loss, s);
        __threadfence();
        unsigned done = atomicAdd(&g_done, 1u);
        if (done == (unsigned)(gridDim.x - 1)) {
            double L = atomicAdd(&g_loss, 0.0);      // fenced read after all adds
            float v = (float)(L * (1.0 / 524288.0)); // / (B*CDIM*T)
            out[LOSS_OFF]     = v;   // commitment_loss
            out[LOSS_OFF + 1] = v;   // codebook_loss (identical in eval forward)
        }
    }
}

// ---------------- launch ----------------
extern "C" void kernel_launch(void* const* d_in, const int* in_sizes, int n_in,
                              void* d_out, int out_size) {
    const float* z     = (const float*)d_in[0];
    const float* w_in  = (const float*)d_in[1];
    const float* b_in  = (const float*)d_in[2];
    const float* w_out = (const float*)d_in[3];
    const float* b_out = (const float*)d_in[4];
    const float* cb    = (const float*)d_in[5];
    float* out = (float*)d_out;

    cudaFuncSetAttribute(rvq_main, cudaFuncAttributeMaxDynamicSharedMemorySize, SMEM_BYTES);

    rvq_prep<<<40, 256>>>(cb, w_in, w_out);
    rvq_main<<<NCTAS, THREADS, SMEM_BYTES>>>(z, b_in, b_out, cb, out);
}

// round 7
// speedup vs baseline: 1.1482x; 1.0446x over previous
#include <cuda_runtime.h>

// ---------------- problem constants ----------------
#define NCB   9
#define BB    16
#define DD    512
#define TT    4096
#define KK    1024
#define CDIM  8

#define TILE     64
#define THREADS  512
#define NCTAS    ((BB * TT) / TILE)     // 1024

// output layout (float32, concatenated)
#define ZQ_OFF     0ll
#define CODES_OFF  33554432ll
#define LAT_OFF    34144256ll
#define LOSS_OFF   38862848ll

// ---------------- smem layout (float offsets) ----------------
#define S_WI    0          // packed [d][c] 4096
#define S_WO    4096       // [c][d] 4096
#define S_CBT   8192       // [c][k] 8192
#define S_C2    16384      // 1024
#define S_BOUT  17408      // 512
#define S_BIN   17920      // 8
#define S_ZE    17928      // [c][p] 8*64 = 512
#define S_EN    18440      // [c][p] 512
#define S_EN2   18952      // 64
#define S_PART  19016      // 64*65 = 4160 (A partials; reused as BESTD/BESTI in B)
#define S_BESTD S_PART                   // 16*64 = 1024
#define S_BESTI (S_PART+1024)            // 1024 ints
#define S_CBQ   23176      // [p*9+c] 576
#define S_LOSS  23752      // 64 doubles = 128 floats (byte 95008, 8-aligned)
#define SMEM_FLOATS 23880
#define SMEM_BYTES  (SMEM_FLOATS*4)   // 95520

// ---------------- device scratch ----------------
__device__ float    g_wi_p[NCB * DD * CDIM];   // [i][d][c]
__device__ float    g_wo_t[NCB * CDIM * DD];   // [i][c][d]
__device__ float    g_cbt [NCB * CDIM * KK];   // [i][c][k] (normalized, transposed)
__device__ float    g_c2  [NCB * KK];
__device__ double   g_loss;
__device__ unsigned g_done;

// ---------------- packed f32x2 helpers ----------------
typedef unsigned long long u64;
__device__ __forceinline__ u64 pk2(float lo, float hi) {
    u64 r; asm("mov.b64 %0,{%1,%2};" : "=l"(r) : "f"(lo), "f"(hi)); return r;
}
__device__ __forceinline__ void upk2(float& lo, float& hi, u64 v) {
    asm("mov.b64 {%0,%1},%2;" : "=f"(lo), "=f"(hi) : "l"(v));
}
__device__ __forceinline__ u64 f2fma(u64 a, u64 b, u64 c) {
    u64 d; asm("fma.rn.f32x2 %0,%1,%2,%3;" : "=l"(d) : "l"(a), "l"(b), "l"(c)); return d;
}
__device__ __forceinline__ u64 f2mul(u64 a, u64 b) {
    u64 d; asm("mul.rn.f32x2 %0,%1,%2;" : "=l"(d) : "l"(a), "l"(b)); return d;
}
__device__ __forceinline__ u64 f2add(u64 a, u64 b) {
    u64 d; asm("add.rn.f32x2 %0,%1,%2;" : "=l"(d) : "l"(a), "l"(b)); return d;
}
__device__ __forceinline__ void cp16(unsigned smaddr, const float* g) {
    asm volatile("cp.async.cg.shared.global [%0], [%1], 16;" :: "r"(smaddr), "l"(g));
}
#define CP_COMMIT() asm volatile("cp.async.commit_group;")
#define CP_WAIT(n)  asm volatile("cp.async.wait_group %0;" :: "n"(n))

// ---------------- prep: normalize + transpose, zero loss ----------------
__global__ void rvq_prep(const float* __restrict__ cb,
                         const float* __restrict__ w_in,
                         const float* __restrict__ w_out) {
    int v = blockIdx.x * blockDim.x + threadIdx.x;
    if (v == 0) { g_loss = 0.0; g_done = 0u; }
    if (v < NCB * KK) {
        int i = v / KK, k = v % KK;
        const float* src = cb + (size_t)v * CDIM;
        float x[CDIM];
#pragma unroll
        for (int c = 0; c < CDIM; c++) x[c] = src[c];
        float ss = 0.f;
#pragma unroll
        for (int c = 0; c < CDIM; c++) ss = fmaf(x[c], x[c], ss);
        float den = fmaxf(__fsqrt_rn(ss), 1e-12f);
        float c2 = 0.f;
#pragma unroll
        for (int c = 0; c < CDIM; c++) {
            float e = __fdiv_rn(x[c], den);   // exact IEEE div, matches reference
            g_cbt[((size_t)i * CDIM + c) * KK + k] = e;
            c2 = fmaf(e, e, c2);
        }
        g_c2[v] = c2;
    }
    for (int idx = v; idx < NCB * DD * CDIM; idx += gridDim.x * blockDim.x) {
        int i = idx / (DD * CDIM), rem = idx % (DD * CDIM);
        int c = rem / DD, d = rem % DD;
        g_wi_p[(size_t)i * DD * CDIM + d * CDIM + c] = w_in[idx];       // idx=[i][c][d]
        int d2 = rem / CDIM, c2i = rem % CDIM;
        g_wo_t[(size_t)i * CDIM * DD + c2i * DD + d2] = w_out[idx];     // idx=[i][d][c]
    }
}

// ---------------- main fused kernel ----------------
extern __shared__ float sm[];

__global__ void __launch_bounds__(THREADS, 1)
rvq_main(const float* __restrict__ z,
         const float* __restrict__ b_in,
         const float* __restrict__ b_out,
         const float* __restrict__ cbraw,
         float* __restrict__ out) {
    const int tid  = threadIdx.x;
    const int pos0 = blockIdx.x * TILE;
    const int b    = pos0 >> 12;
    const int t0   = pos0 & (TT - 1);
    const unsigned smb = (unsigned)__cvta_generic_to_shared(sm);

    const int p  = tid & 63;          // position (A/C mapping)
    const int sl = tid >> 6;          // 0..7 d-chunk
    const int d0 = sl << 6;

    // B mapping: 16 k-slices x 32 position-pairs
    const int pb  = tid & 31;         // serves positions pb and pb+32
    const int slb = tid >> 5;         // 0..15, 64 codes each

    // residual lives in REGISTERS: r[dd] = residual[d0+dd][p]
    const float* zc = z + ((size_t)b * DD + d0) * TT + t0 + p;
    float r[64];
#pragma unroll
    for (int dd = 0; dd < 64; dd++) r[dd] = zc[(size_t)dd * TT];

    double lossAcc = 0.0;

    for (int i = 0; i < NCB; ++i) {
        __syncthreads();   // prev iter's C (reads WO/CBQ) done before restage

        // ---- stage weights via cp.async (3 groups) ----
        if (tid < CDIM) sm[S_BIN + tid] = b_in[(size_t)i * CDIM + tid];
        {
            const float* wi = g_wi_p + (size_t)i * DD * CDIM;
            cp16(smb + (S_WI + tid * 4) * 4,        wi + tid * 4);
            cp16(smb + (S_WI + 2048 + tid * 4) * 4, wi + 2048 + tid * 4);
        }
        CP_COMMIT();   // group: wi
        {
            const float* ct = g_cbt + (size_t)i * CDIM * KK;
#pragma unroll
            for (int r4 = 0; r4 < 4; r4++)
                cp16(smb + (S_CBT + r4 * 2048 + tid * 4) * 4, ct + r4 * 2048 + tid * 4);
            if (tid < 256) cp16(smb + (S_C2 + tid * 4) * 4, g_c2 + (size_t)i * KK + tid * 4);
        }
        CP_COMMIT();   // group: cbt + c2
        {
            const float* wo = g_wo_t + (size_t)i * CDIM * DD;
            cp16(smb + (S_WO + tid * 4) * 4,        wo + tid * 4);
            cp16(smb + (S_WO + 2048 + tid * 4) * 4, wo + 2048 + tid * 4);
            if (tid < 128) cp16(smb + (S_BOUT + tid * 4) * 4, b_out + (size_t)i * DD + tid * 4);
        }
        CP_COMMIT();   // group: wo + bout

        CP_WAIT(2);    // wi ready
        __syncthreads();

        // ---- Phase A: partial z_e over this thread's 64-d register chunk ----
        {
            u64 a01 = 0, a23 = 0, a45 = 0, a67 = 0;
#pragma unroll
            for (int dd = 0; dd < 64; dd++) {
                float rv = r[dd];
                u64 rr = pk2(rv, rv);
                ulonglong2 wA = *reinterpret_cast<const ulonglong2*>(sm + S_WI + (d0 + dd) * 8);
                ulonglong2 wB = *reinterpret_cast<const ulonglong2*>(sm + S_WI + (d0 + dd) * 8 + 4);
                a01 = f2fma(wA.x, rr, a01);
                a23 = f2fma(wA.y, rr, a23);
                a45 = f2fma(wB.x, rr, a45);
                a67 = f2fma(wB.y, rr, a67);
            }
            float v0,v1,v2,v3,v4,v5,v6,v7;
            upk2(v0,v1,a01); upk2(v2,v3,a23); upk2(v4,v5,a45); upk2(v6,v7,a67);
            // PART element (p, c, sl) at p*65 + c*8 + sl
            float* pbuf = sm + S_PART + p * 65 + sl;
            pbuf[0]=v0; pbuf[8]=v1; pbuf[16]=v2; pbuf[24]=v3;
            pbuf[32]=v4; pbuf[40]=v5; pbuf[48]=v6; pbuf[56]=v7;
        }
        __syncthreads();

        // ---- combineA + normalize (tid<64): z_e, en, en2 (done ONCE per position) ----
        if (tid < 64) {
            float zv[8];
#pragma unroll
            for (int c = 0; c < 8; c++) {
                const float* pbuf = sm + S_PART + tid * 65 + c * 8;
                float s = pbuf[0];
#pragma unroll
                for (int s8 = 1; s8 < 8; s8++) s += pbuf[s8];
                zv[c] = s + sm[S_BIN + c];
                sm[S_ZE + c * 64 + tid] = zv[c];
            }
            float ss = 0.f;
#pragma unroll
            for (int c = 0; c < 8; c++) ss = fmaf(zv[c], zv[c], ss);
            float den = fmaxf(__fsqrt_rn(ss), 1e-12f);
            float e[8], en2 = 0.f;
#pragma unroll
            for (int c = 0; c < 8; c++) { e[c] = __fdiv_rn(zv[c], den); sm[S_EN + c * 64 + tid] = e[c]; }
#pragma unroll
            for (int c = 0; c < 8; c++) en2 = fmaf(e[c], e[c], en2);
            sm[S_EN2 + tid] = en2;
        }
        CP_WAIT(1);   // cbt + c2 ready
        __syncthreads();

        // ---- Phase B: 2 positions per thread, 64 codes per slice ----
        {
            // lane-distributed en reads (full-width wavefronts, cheap)
            u64 eP[8], eQ[8];
#pragma unroll
            for (int c = 0; c < 8; c++) {
                float ep = sm[S_EN + c * 64 + pb];
                float eq = sm[S_EN + c * 64 + pb + 32];
                eP[c] = pk2(ep, ep);
                eQ[c] = pk2(eq, eq);
            }
            float en2P = sm[S_EN2 + pb];
            float en2Q = sm[S_EN2 + pb + 32];
            u64 e2sP = pk2(en2P, en2P);
            u64 e2sQ = pk2(en2Q, en2Q);
            u64 m2s  = pk2(-2.f, -2.f);

            const int k0 = slb << 6;
            // two independent argmin chains per position (exact merge below)
            float bPx = 3.402823466e38f, bPy = bPx, bQx = bPx, bQy = bPx;
            int   iPx = k0, iPy = k0, iQx = k0, iQy = k0;
#pragma unroll 4
            for (int q = 0; q < 16; ++q) {
                const int kb = k0 + (q << 2);
                ulonglong2 c0 = *reinterpret_cast<const ulonglong2*>(sm + S_CBT + 0*KK + kb);
                ulonglong2 c1 = *reinterpret_cast<const ulonglong2*>(sm + S_CBT + 1*KK + kb);
                ulonglong2 c2r= *reinterpret_cast<const ulonglong2*>(sm + S_CBT + 2*KK + kb);
                ulonglong2 c3 = *reinterpret_cast<const ulonglong2*>(sm + S_CBT + 3*KK + kb);
                ulonglong2 c4 = *reinterpret_cast<const ulonglong2*>(sm + S_CBT + 4*KK + kb);
                ulonglong2 c5 = *reinterpret_cast<const ulonglong2*>(sm + S_CBT + 5*KK + kb);
                ulonglong2 c6 = *reinterpret_cast<const ulonglong2*>(sm + S_CBT + 6*KK + kb);
                ulonglong2 c7 = *reinterpret_cast<const ulonglong2*>(sm + S_CBT + 7*KK + kb);
                ulonglong2 c2p = *reinterpret_cast<const ulonglong2*>(sm + S_C2 + kb);

                // position P, codes (kb,kb+1) and (kb+2,kb+3)
                u64 dAP = f2mul(eP[0], c0.x);
                dAP = f2fma(eP[1], c1.x, dAP); dAP = f2fma(eP[2], c2r.x, dAP);
                dAP = f2fma(eP[3], c3.x, dAP); dAP = f2fma(eP[4], c4.x, dAP);
                dAP = f2fma(eP[5], c5.x, dAP); dAP = f2fma(eP[6], c6.x, dAP);
                dAP = f2fma(eP[7], c7.x, dAP);
                u64 dBP = f2mul(eP[0], c0.y);
                dBP = f2fma(eP[1], c1.y, dBP); dBP = f2fma(eP[2], c2r.y, dBP);
                dBP = f2fma(eP[3], c3.y, dBP); dBP = f2fma(eP[4], c4.y, dBP);
                dBP = f2fma(eP[5], c5.y, dBP); dBP = f2fma(eP[6], c6.y, dBP);
                dBP = f2fma(eP[7], c7.y, dBP);
                // position Q (reuses the same code registers — broadcast amortized)
                u64 dAQ = f2mul(eQ[0], c0.x);
                dAQ = f2fma(eQ[1], c1.x, dAQ); dAQ = f2fma(eQ[2], c2r.x, dAQ);
                dAQ = f2fma(eQ[3], c3.x, dAQ); dAQ = f2fma(eQ[4], c4.x, dAQ);
                dAQ = f2fma(eQ[5], c5.x, dAQ); dAQ = f2fma(eQ[6], c6.x, dAQ);
                dAQ = f2fma(eQ[7], c7.x, dAQ);
                u64 dBQ = f2mul(eQ[0], c0.y);
                dBQ = f2fma(eQ[1], c1.y, dBQ); dBQ = f2fma(eQ[2], c2r.y, dBQ);
                dBQ = f2fma(eQ[3], c3.y, dBQ); dBQ = f2fma(eQ[4], c4.y, dBQ);
                dBQ = f2fma(eQ[5], c5.y, dBQ); dBQ = f2fma(eQ[6], c6.y, dBQ);
                dBQ = f2fma(eQ[7], c7.y, dBQ);

                u64 sAP = f2add(f2fma(m2s, dAP, e2sP), c2p.x);   // (en2-2dot)+c2, per-lane exact
                u64 sBP = f2add(f2fma(m2s, dBP, e2sP), c2p.y);
                u64 sAQ = f2add(f2fma(m2s, dAQ, e2sQ), c2p.x);
                u64 sBQ = f2add(f2fma(m2s, dBQ, e2sQ), c2p.y);

                float f0,f1,f2,f3;
                upk2(f0,f1,sAP); upk2(f2,f3,sBP);
                if (f0 < bPx) { bPx = f0; iPx = kb;     }   // strict <: chain keeps lowest q
                if (f1 < bPx) { bPx = f1; iPx = kb + 1; }
                if (f2 < bPy) { bPy = f2; iPy = kb + 2; }
                if (f3 < bPy) { bPy = f3; iPy = kb + 3; }
                upk2(f0,f1,sAQ); upk2(f2,f3,sBQ);
                if (f0 < bQx) { bQx = f0; iQx = kb;     }
                if (f1 < bQx) { bQx = f1; iQx = kb + 1; }
                if (f2 < bQy) { bQy = f2; iQy = kb + 2; }
                if (f3 < bQy) { bQy = f3; iQy = kb + 3; }
            }
            // merge chains with exact lowest-index tie-break
            float bP = bPx; int iP = iPx;
            if (bPy < bP || (bPy == bP && iPy < iP)) { bP = bPy; iP = iPy; }
            float bQ = bQx; int iQ = iQx;
            if (bQy < bQ || (bQy == bQ && iQy < iQ)) { bQ = bQy; iQ = iQy; }
            sm[S_BESTD + (slb << 6) + pb]      = bP;
            sm[S_BESTD + (slb << 6) + pb + 32] = bQ;
            reinterpret_cast<int*>(sm + S_BESTI)[(slb << 6) + pb]      = iP;
            reinterpret_cast<int*>(sm + S_BESTI)[(slb << 6) + pb + 32] = iQ;
        }
        __syncthreads();

        // ---- combineB: latents, codes, gather raw codebook, loss ----
        out[LAT_OFF + ((size_t)(b * (NCB*CDIM) + i*CDIM + sl)) * TT + t0 + p] =
            sm[S_ZE + sl * 64 + p];
        if (tid < 64) {
            float bestd = sm[S_BESTD + tid];
            int   bi    = reinterpret_cast<int*>(sm + S_BESTI)[tid];
#pragma unroll
            for (int s = 1; s < 16; s++) {    // ascending k ranges: strict < keeps lowest k
                float d2 = sm[S_BESTD + (s << 6) + tid];
                int   i2 = reinterpret_cast<int*>(sm + S_BESTI)[(s << 6) + tid];
                if (d2 < bestd) { bestd = d2; bi = i2; }
            }
            out[CODES_OFF + ((size_t)(b * NCB + i)) * TT + t0 + tid] = (float)bi;
            const float* cr = cbraw + ((size_t)i * KK + bi) * CDIM;
            double ls = 0.0;
#pragma unroll
            for (int cc = 0; cc < 8; cc++) {
                float cv = __ldg(cr + cc);
                sm[S_CBQ + tid * 9 + cc] = cv;
                float df = sm[S_ZE + cc * 64 + tid] - cv;
                ls += (double)(df * df);
            }
            lossAcc += ls;
        }
        CP_WAIT(0);   // wo + bout ready
        __syncthreads();

        // ---- Phase C: r[dd] -= w_out[:, d0+dd] . q[p] + b_out  (r in regs) ----
        {
            u64 qq[8];
#pragma unroll
            for (int c = 0; c < 8; c++) { float qv = sm[S_CBQ + p * 9 + c]; qq[c] = pk2(qv, qv); }
#pragma unroll
            for (int dg = 0; dg < 16; dg++) {
                const int d = d0 + dg * 4;
                ulonglong2 w0 = *reinterpret_cast<const ulonglong2*>(sm + S_WO + 0*DD + d);
                ulonglong2 w1 = *reinterpret_cast<const ulonglong2*>(sm + S_WO + 1*DD + d);
                ulonglong2 w2 = *reinterpret_cast<const ulonglong2*>(sm + S_WO + 2*DD + d);
                ulonglong2 w3 = *reinterpret_cast<const ulonglong2*>(sm + S_WO + 3*DD + d);
                ulonglong2 w4 = *reinterpret_cast<const ulonglong2*>(sm + S_WO + 4*DD + d);
                ulonglong2 w5 = *reinterpret_cast<const ulonglong2*>(sm + S_WO + 5*DD + d);
                ulonglong2 w6 = *reinterpret_cast<const ulonglong2*>(sm + S_WO + 6*DD + d);
                ulonglong2 w7 = *reinterpret_cast<const ulonglong2*>(sm + S_WO + 7*DD + d);
                u64 aA = f2mul(qq[0], w0.x);
                aA = f2fma(qq[1], w1.x, aA); aA = f2fma(qq[2], w2.x, aA);
                aA = f2fma(qq[3], w3.x, aA); aA = f2fma(qq[4], w4.x, aA);
                aA = f2fma(qq[5], w5.x, aA); aA = f2fma(qq[6], w6.x, aA);
                aA = f2fma(qq[7], w7.x, aA);
                u64 aB = f2mul(qq[0], w0.y);
                aB = f2fma(qq[1], w1.y, aB); aB = f2fma(qq[2], w2.y, aB);
                aB = f2fma(qq[3], w3.y, aB); aB = f2fma(qq[4], w4.y, aB);
                aB = f2fma(qq[5], w5.y, aB); aB = f2fma(qq[6], w6.y, aB);
                aB = f2fma(qq[7], w7.y, aB);
                ulonglong2 bo = *reinterpret_cast<const ulonglong2*>(sm + S_BOUT + d);
                aA = f2add(aA, bo.x);
                aB = f2add(aB, bo.y);
                float a0,a1,a2,a3;
                upk2(a0,a1,aA); upk2(a2,a3,aB);
                r[dg*4    ] -= a0;
                r[dg*4 + 1] -= a1;
                r[dg*4 + 2] -= a2;
                r[dg*4 + 3] -= a3;
            }
        }
    }

    // ---- epilogue: z_q = z - r_final (r in regs, coalesced global) ----
    {
        float* oq = out + ZQ_OFF + ((size_t)(b * DD + d0)) * TT + t0 + p;
#pragma unroll
        for (int dd = 0; dd < 64; dd++)
            oq[(size_t)dd * TT] = zc[(size_t)dd * TT] - r[dd];
    }

    // ---- loss: deterministic in-block sum, one atomic; last CTA writes scalars ----
    __syncthreads();
    double* lb = reinterpret_cast<double*>(sm + S_LOSS);
    if (tid < 64) lb[tid] = lossAcc;
    __syncthreads();
    if (tid == 0) {
        double s = 0.0;
        for (int j = 0; j < 64; j++) s += lb[j];
        atomicAdd(&g_loss, s);
        __threadfence();
        unsigned done = atomicAdd(&g_done, 1u);
        if (done == (unsigned)(gridDim.x - 1)) {
            double L = atomicAdd(&g_loss, 0.0);      // fenced read after all adds
            float v = (float)(L * (1.0 / 524288.0)); // / (B*CDIM*T)
            out[LOSS_OFF]     = v;   // commitment_loss
            out[LOSS_OFF + 1] = v;   // codebook_loss (identical in eval forward)
        }
    }
}

// ---------------- launch ----------------
extern "C" void kernel_launch(void* const* d_in, const int* in_sizes, int n_in,
                              void* d_out, int out_size) {
    const float* z     = (const float*)d_in[0];
    const float* w_in  = (const float*)d_in[1];
    const float* b_in  = (const float*)d_in[2];
    const float* w_out = (const float*)d_in[3];
    const float* b_out = (const float*)d_in[4];
    const float* cb    = (const float*)d_in[5];
    float* out = (float*)d_out;

    cudaFuncSetAttribute(rvq_main, cudaFuncAttributeMaxDynamicSharedMemorySize, SMEM_BYTES);

    rvq_prep<<<40, 256>>>(cb, w_in, w_out);
    rvq_main<<<NCTAS, THREADS, SMEM_BYTES>>>(z, b_in, b_out, cb, out);
}

// round 8
// speedup vs baseline: 1.2386x; 1.0787x over previous
#include <cuda_runtime.h>

// ---------------- problem constants ----------------
#define NCB   9
#define BB    16
#define DD    512
#define TT    4096
#define KK    1024
#define CDIM  8

#define TILE     64
#define THREADS  512
#define NCTAS    ((BB * TT) / TILE)     // 1024

// output layout (float32, concatenated)
#define ZQ_OFF     0ll
#define CODES_OFF  33554432ll
#define LAT_OFF    34144256ll
#define LOSS_OFF   38862848ll

// ---------------- smem layout (float offsets) ----------------
#define S_WI    0          // packed [d][c] 4096
#define S_WO    4096       // [c][d] 4096
#define S_CBT   8192       // [c][k] 8192
#define S_C2    16384      // 1024
#define S_BOUT  17408      // 512
#define S_BIN   17920      // 8
#define S_ZE    17928      // [c][p] 8*64 = 512
#define S_EN    18440      // [c][p] 512
#define S_EN2   18952      // 64
#define S_PART  19016      // 64*129 = 8256 (A partials [p][c*16+ch]; reused for BESTD/BESTI)
#define S_BESTD S_PART                   // 16*64 = 1024
#define S_BESTI (S_PART+1024)            // 1024 ints
#define S_CBQ   27272      // [p*9+c] 576
#define S_LOSS  27848      // 64 doubles = 128 floats (byte 111392, 8-aligned)
#define SMEM_FLOATS 27976
#define SMEM_BYTES  (SMEM_FLOATS*4)   // 111904

// ---------------- device scratch ----------------
__device__ float    g_wi_p[NCB * DD * CDIM];   // [i][d][c]
__device__ float    g_wo_t[NCB * CDIM * DD];   // [i][c][d]
__device__ float    g_cbt [NCB * CDIM * KK];   // [i][c][k] (normalized, transposed)
__device__ float    g_c2  [NCB * KK];
__device__ double   g_loss;
__device__ unsigned g_done;

// ---------------- packed f32x2 helpers ----------------
typedef unsigned long long u64;
__device__ __forceinline__ u64 pk2(float lo, float hi) {
    u64 r; asm("mov.b64 %0,{%1,%2};" : "=l"(r) : "f"(lo), "f"(hi)); return r;
}
__device__ __forceinline__ void upk2(float& lo, float& hi, u64 v) {
    asm("mov.b64 {%0,%1},%2;" : "=f"(lo), "=f"(hi) : "l"(v));
}
__device__ __forceinline__ u64 f2fma(u64 a, u64 b, u64 c) {
    u64 d; asm("fma.rn.f32x2 %0,%1,%2,%3;" : "=l"(d) : "l"(a), "l"(b), "l"(c)); return d;
}
__device__ __forceinline__ u64 f2mul(u64 a, u64 b) {
    u64 d; asm("mul.rn.f32x2 %0,%1,%2;" : "=l"(d) : "l"(a), "l"(b)); return d;
}
__device__ __forceinline__ u64 f2add(u64 a, u64 b) {
    u64 d; asm("add.rn.f32x2 %0,%1,%2;" : "=l"(d) : "l"(a), "l"(b)); return d;
}
__device__ __forceinline__ void cp16(unsigned smaddr, const float* g) {
    asm volatile("cp.async.cg.shared.global [%0], [%1], 16;" :: "r"(smaddr), "l"(g));
}
#define CP_COMMIT() asm volatile("cp.async.commit_group;")
#define CP_WAIT(n)  asm volatile("cp.async.wait_group %0;" :: "n"(n))

// ---------------- prep: normalize + transpose, zero loss ----------------
__global__ void rvq_prep(const float* __restrict__ cb,
                         const float* __restrict__ w_in,
                         const float* __restrict__ w_out) {
    int v = blockIdx.x * blockDim.x + threadIdx.x;
    if (v == 0) { g_loss = 0.0; g_done = 0u; }
    if (v < NCB * KK) {
        int i = v / KK, k = v % KK;
        const float* src = cb + (size_t)v * CDIM;
        float x[CDIM];
#pragma unroll
        for (int c = 0; c < CDIM; c++) x[c] = src[c];
        float ss = 0.f;
#pragma unroll
        for (int c = 0; c < CDIM; c++) ss = fmaf(x[c], x[c], ss);
        float den = fmaxf(__fsqrt_rn(ss), 1e-12f);
        float c2 = 0.f;
#pragma unroll
        for (int c = 0; c < CDIM; c++) {
            float e = __fdiv_rn(x[c], den);   // exact IEEE div, matches reference
            g_cbt[((size_t)i * CDIM + c) * KK + k] = e;
            c2 = fmaf(e, e, c2);
        }
        g_c2[v] = c2;
    }
    for (int idx = v; idx < NCB * DD * CDIM; idx += gridDim.x * blockDim.x) {
        int i = idx / (DD * CDIM), rem = idx % (DD * CDIM);
        int c = rem / DD, d = rem % DD;
        g_wi_p[(size_t)i * DD * CDIM + d * CDIM + c] = w_in[idx];       // idx=[i][c][d]
        int d2 = rem / CDIM, c2i = rem % CDIM;
        g_wo_t[(size_t)i * CDIM * DD + c2i * DD + d2] = w_out[idx];     // idx=[i][d][c]
    }
}

// ---------------- main fused kernel ----------------
extern __shared__ float sm[];

__global__ void __launch_bounds__(THREADS, 1)
rvq_main(const float* __restrict__ z,
         const float* __restrict__ b_in,
         const float* __restrict__ b_out,
         const float* __restrict__ cbraw,
         float* __restrict__ out) {
    const int tid  = threadIdx.x;
    const int pos0 = blockIdx.x * TILE;
    const int b    = pos0 >> 12;
    const int t0   = pos0 & (TT - 1);
    const unsigned smb = (unsigned)__cvta_generic_to_shared(sm);

    // A/C mapping: 2 positions (pA, pA+32) x 32-dim chunk
    const int pA = tid & 31;
    const int ch = tid >> 5;          // 0..15
    const int d0 = ch << 5;

    // B mapping: 16 k-slices x 32 position-pairs (same as A/C pair)
    const int pb  = pA;
    const int slb = ch;

    // latents/ZE mapping
    const int p64 = tid & 63;
    const int sl8 = tid >> 6;

    // residual in REGISTERS: rA[dd]=res[d0+dd][pA], rB[dd]=res[d0+dd][pA+32]
    const float* zcA = z + ((size_t)b * DD + d0) * TT + t0 + pA;
    const float* zcB = zcA + 32;
    float rA[32], rB[32];
#pragma unroll
    for (int dd = 0; dd < 32; dd++) { rA[dd] = zcA[(size_t)dd * TT]; rB[dd] = zcB[(size_t)dd * TT]; }

    double lossAcc = 0.0;

    for (int i = 0; i < NCB; ++i) {
        __syncthreads();   // prev iter's C done before restage

        // ---- stage weights via cp.async (3 groups) ----
        if (tid < CDIM) sm[S_BIN + tid] = b_in[(size_t)i * CDIM + tid];
        {
            const float* wi = g_wi_p + (size_t)i * DD * CDIM;
            cp16(smb + (S_WI + tid * 4) * 4,        wi + tid * 4);
            cp16(smb + (S_WI + 2048 + tid * 4) * 4, wi + 2048 + tid * 4);
        }
        CP_COMMIT();   // group: wi
        {
            const float* ct = g_cbt + (size_t)i * CDIM * KK;
#pragma unroll
            for (int r4 = 0; r4 < 4; r4++)
                cp16(smb + (S_CBT + r4 * 2048 + tid * 4) * 4, ct + r4 * 2048 + tid * 4);
            if (tid < 256) cp16(smb + (S_C2 + tid * 4) * 4, g_c2 + (size_t)i * KK + tid * 4);
        }
        CP_COMMIT();   // group: cbt + c2
        {
            const float* wo = g_wo_t + (size_t)i * CDIM * DD;
            cp16(smb + (S_WO + tid * 4) * 4,        wo + tid * 4);
            cp16(smb + (S_WO + 2048 + tid * 4) * 4, wo + 2048 + tid * 4);
            if (tid < 128) cp16(smb + (S_BOUT + tid * 4) * 4, b_out + (size_t)i * DD + tid * 4);
        }
        CP_COMMIT();   // group: wo + bout

        CP_WAIT(2);    // wi ready
        __syncthreads();

        // ---- Phase A: partials for 2 positions over 32-dim chunk (shared w loads) ----
        {
            u64 aP01=0, aP23=0, aP45=0, aP67=0;
            u64 aQ01=0, aQ23=0, aQ45=0, aQ67=0;
#pragma unroll
            for (int dd = 0; dd < 32; dd++) {
                ulonglong2 wA = *reinterpret_cast<const ulonglong2*>(sm + S_WI + (d0 + dd) * 8);
                ulonglong2 wB = *reinterpret_cast<const ulonglong2*>(sm + S_WI + (d0 + dd) * 8 + 4);
                u64 rP = pk2(rA[dd], rA[dd]);
                u64 rQ = pk2(rB[dd], rB[dd]);
                aP01 = f2fma(wA.x, rP, aP01); aQ01 = f2fma(wA.x, rQ, aQ01);
                aP23 = f2fma(wA.y, rP, aP23); aQ23 = f2fma(wA.y, rQ, aQ23);
                aP45 = f2fma(wB.x, rP, aP45); aQ45 = f2fma(wB.x, rQ, aQ45);
                aP67 = f2fma(wB.y, rP, aP67); aQ67 = f2fma(wB.y, rQ, aQ67);
            }
            float v0,v1,v2,v3,v4,v5,v6,v7;
            float* pbA = sm + S_PART + pA * 129 + ch;          // [p][c*16+ch]
            upk2(v0,v1,aP01); upk2(v2,v3,aP23); upk2(v4,v5,aP45); upk2(v6,v7,aP67);
            pbA[0]=v0;  pbA[16]=v1; pbA[32]=v2; pbA[48]=v3;
            pbA[64]=v4; pbA[80]=v5; pbA[96]=v6; pbA[112]=v7;
            float* pbB = sm + S_PART + (pA + 32) * 129 + ch;
            upk2(v0,v1,aQ01); upk2(v2,v3,aQ23); upk2(v4,v5,aQ45); upk2(v6,v7,aQ67);
            pbB[0]=v0;  pbB[16]=v1; pbB[32]=v2; pbB[48]=v3;
            pbB[64]=v4; pbB[80]=v5; pbB[96]=v6; pbB[112]=v7;
        }
        __syncthreads();

        // ---- combineA + normalize (tid<64): z_e, en, en2 ----
        if (tid < 64) {
            float zv[8];
#pragma unroll
            for (int c = 0; c < 8; c++) {
                const float* pbuf = sm + S_PART + tid * 129 + c * 16;
                float s = pbuf[0];
#pragma unroll
                for (int j = 1; j < 16; j++) s += pbuf[j];   // ascending dim-chunk order
                zv[c] = s + sm[S_BIN + c];
                sm[S_ZE + c * 64 + tid] = zv[c];
            }
            float ss = 0.f;
#pragma unroll
            for (int c = 0; c < 8; c++) ss = fmaf(zv[c], zv[c], ss);
            float den = fmaxf(__fsqrt_rn(ss), 1e-12f);
            float e[8], en2 = 0.f;
#pragma unroll
            for (int c = 0; c < 8; c++) { e[c] = __fdiv_rn(zv[c], den); sm[S_EN + c * 64 + tid] = e[c]; }
#pragma unroll
            for (int c = 0; c < 8; c++) en2 = fmaf(e[c], e[c], en2);
            sm[S_EN2 + tid] = en2;
        }
        CP_WAIT(1);   // cbt + c2 ready
        __syncthreads();

        // ---- Phase B: 2 positions per thread, 64 codes per slice ----
        {
            u64 eP[8], eQ[8];
#pragma unroll
            for (int c = 0; c < 8; c++) {
                float ep = sm[S_EN + c * 64 + pb];
                float eq = sm[S_EN + c * 64 + pb + 32];
                eP[c] = pk2(ep, ep);
                eQ[c] = pk2(eq, eq);
            }
            float en2P = sm[S_EN2 + pb];
            float en2Q = sm[S_EN2 + pb + 32];
            u64 e2sP = pk2(en2P, en2P);
            u64 e2sQ = pk2(en2Q, en2Q);
            u64 m2s  = pk2(-2.f, -2.f);

            const int k0 = slb << 6;
            float bPx = 3.402823466e38f, bPy = bPx, bQx = bPx, bQy = bPx;
            int   iPx = k0, iPy = k0, iQx = k0, iQy = k0;
#pragma unroll 4
            for (int q = 0; q < 16; ++q) {
                const int kb = k0 + (q << 2);
                ulonglong2 c0 = *reinterpret_cast<const ulonglong2*>(sm + S_CBT + 0*KK + kb);
                ulonglong2 c1 = *reinterpret_cast<const ulonglong2*>(sm + S_CBT + 1*KK + kb);
                ulonglong2 c2r= *reinterpret_cast<const ulonglong2*>(sm + S_CBT + 2*KK + kb);
                ulonglong2 c3 = *reinterpret_cast<const ulonglong2*>(sm + S_CBT + 3*KK + kb);
                ulonglong2 c4 = *reinterpret_cast<const ulonglong2*>(sm + S_CBT + 4*KK + kb);
                ulonglong2 c5 = *reinterpret_cast<const ulonglong2*>(sm + S_CBT + 5*KK + kb);
                ulonglong2 c6 = *reinterpret_cast<const ulonglong2*>(sm + S_CBT + 6*KK + kb);
                ulonglong2 c7 = *reinterpret_cast<const ulonglong2*>(sm + S_CBT + 7*KK + kb);
                ulonglong2 c2p = *reinterpret_cast<const ulonglong2*>(sm + S_C2 + kb);

                u64 dAP = f2mul(eP[0], c0.x);
                dAP = f2fma(eP[1], c1.x, dAP); dAP = f2fma(eP[2], c2r.x, dAP);
                dAP = f2fma(eP[3], c3.x, dAP); dAP = f2fma(eP[4], c4.x, dAP);
                dAP = f2fma(eP[5], c5.x, dAP); dAP = f2fma(eP[6], c6.x, dAP);
                dAP = f2fma(eP[7], c7.x, dAP);
                u64 dBP = f2mul(eP[0], c0.y);
                dBP = f2fma(eP[1], c1.y, dBP); dBP = f2fma(eP[2], c2r.y, dBP);
                dBP = f2fma(eP[3], c3.y, dBP); dBP = f2fma(eP[4], c4.y, dBP);
                dBP = f2fma(eP[5], c5.y, dBP); dBP = f2fma(eP[6], c6.y, dBP);
                dBP = f2fma(eP[7], c7.y, dBP);
                u64 dAQ = f2mul(eQ[0], c0.x);
                dAQ = f2fma(eQ[1], c1.x, dAQ); dAQ = f2fma(eQ[2], c2r.x, dAQ);
                dAQ = f2fma(eQ[3], c3.x, dAQ); dAQ = f2fma(eQ[4], c4.x, dAQ);
                dAQ = f2fma(eQ[5], c5.x, dAQ); dAQ = f2fma(eQ[6], c6.x, dAQ);
                dAQ = f2fma(eQ[7], c7.x, dAQ);
                u64 dBQ = f2mul(eQ[0], c0.y);
                dBQ = f2fma(eQ[1], c1.y, dBQ); dBQ = f2fma(eQ[2], c2r.y, dBQ);
                dBQ = f2fma(eQ[3], c3.y, dBQ); dBQ = f2fma(eQ[4], c4.y, dBQ);
                dBQ = f2fma(eQ[5], c5.y, dBQ); dBQ = f2fma(eQ[6], c6.y, dBQ);
                dBQ = f2fma(eQ[7], c7.y, dBQ);

                u64 sAP = f2add(f2fma(m2s, dAP, e2sP), c2p.x);   // (en2-2dot)+c2, per-lane exact
                u64 sBP = f2add(f2fma(m2s, dBP, e2sP), c2p.y);
                u64 sAQ = f2add(f2fma(m2s, dAQ, e2sQ), c2p.x);
                u64 sBQ = f2add(f2fma(m2s, dBQ, e2sQ), c2p.y);

                float f0,f1,f2,f3;
                upk2(f0,f1,sAP); upk2(f2,f3,sBP);
                if (f0 < bPx) { bPx = f0; iPx = kb;     }   // strict <: chain keeps lowest q
                if (f1 < bPx) { bPx = f1; iPx = kb + 1; }
                if (f2 < bPy) { bPy = f2; iPy = kb + 2; }
                if (f3 < bPy) { bPy = f3; iPy = kb + 3; }
                upk2(f0,f1,sAQ); upk2(f2,f3,sBQ);
                if (f0 < bQx) { bQx = f0; iQx = kb;     }
                if (f1 < bQx) { bQx = f1; iQx = kb + 1; }
                if (f2 < bQy) { bQy = f2; iQy = kb + 2; }
                if (f3 < bQy) { bQy = f3; iQy = kb + 3; }
            }
            // merge chains with exact lowest-index tie-break
            float bP = bPx; int iP = iPx;
            if (bPy < bP || (bPy == bP && iPy < iP)) { bP = bPy; iP = iPy; }
            float bQ = bQx; int iQ = iQx;
            if (bQy < bQ || (bQy == bQ && iQy < iQ)) { bQ = bQy; iQ = iQy; }
            sm[S_BESTD + (slb << 6) + pb]      = bP;
            sm[S_BESTD + (slb << 6) + pb + 32] = bQ;
            reinterpret_cast<int*>(sm + S_BESTI)[(slb << 6) + pb]      = iP;
            reinterpret_cast<int*>(sm + S_BESTI)[(slb << 6) + pb + 32] = iQ;
        }
        __syncthreads();

        // ---- combineB: latents, codes, gather raw codebook, loss ----
        out[LAT_OFF + ((size_t)(b * (NCB*CDIM) + i*CDIM + sl8)) * TT + t0 + p64] =
            sm[S_ZE + sl8 * 64 + p64];
        if (tid < 64) {
            float bestd = sm[S_BESTD + tid];
            int   bi    = reinterpret_cast<int*>(sm + S_BESTI)[tid];
#pragma unroll
            for (int s = 1; s < 16; s++) {    // ascending k ranges: strict < keeps lowest k
                float d2 = sm[S_BESTD + (s << 6) + tid];
                int   i2 = reinterpret_cast<int*>(sm + S_BESTI)[(s << 6) + tid];
                if (d2 < bestd) { bestd = d2; bi = i2; }
            }
            out[CODES_OFF + ((size_t)(b * NCB + i)) * TT + t0 + tid] = (float)bi;
            const float* cr = cbraw + ((size_t)i * KK + bi) * CDIM;
            double ls = 0.0;
#pragma unroll
            for (int cc = 0; cc < 8; cc++) {
                float cv = __ldg(cr + cc);
                sm[S_CBQ + tid * 9 + cc] = cv;
                float df = sm[S_ZE + cc * 64 + tid] - cv;
                ls += (double)(df * df);
            }
            lossAcc += ls;
        }
        CP_WAIT(0);   // wo + bout ready
        __syncthreads();

        // ---- Phase C: both positions' residuals updated with shared w loads ----
        {
            u64 qqA[8], qqB[8];
#pragma unroll
            for (int c = 0; c < 8; c++) {
                float qa = sm[S_CBQ + pA * 9 + c];
                float qb = sm[S_CBQ + (pA + 32) * 9 + c];
                qqA[c] = pk2(qa, qa);
                qqB[c] = pk2(qb, qb);
            }
#pragma unroll
            for (int dg = 0; dg < 8; dg++) {
                const int d = d0 + dg * 4;
                ulonglong2 w0 = *reinterpret_cast<const ulonglong2*>(sm + S_WO + 0*DD + d);
                u64 aA = f2mul(qqA[0], w0.x);
                u64 aB = f2mul(qqA[0], w0.y);
                u64 bA = f2mul(qqB[0], w0.x);
                u64 bB = f2mul(qqB[0], w0.y);
                ulonglong2 w1 = *reinterpret_cast<const ulonglong2*>(sm + S_WO + 1*DD + d);
                aA = f2fma(qqA[1], w1.x, aA); aB = f2fma(qqA[1], w1.y, aB);
                bA = f2fma(qqB[1], w1.x, bA); bB = f2fma(qqB[1], w1.y, bB);
                ulonglong2 w2 = *reinterpret_cast<const ulonglong2*>(sm + S_WO + 2*DD + d);
                aA = f2fma(qqA[2], w2.x, aA); aB = f2fma(qqA[2], w2.y, aB);
                bA = f2fma(qqB[2], w2.x, bA); bB = f2fma(qqB[2], w2.y, bB);
                ulonglong2 w3 = *reinterpret_cast<const ulonglong2*>(sm + S_WO + 3*DD + d);
                aA = f2fma(qqA[3], w3.x, aA); aB = f2fma(qqA[3], w3.y, aB);
                bA = f2fma(qqB[3], w3.x, bA); bB = f2fma(qqB[3], w3.y, bB);
                ulonglong2 w4 = *reinterpret_cast<const ulonglong2*>(sm + S_WO + 4*DD + d);
                aA = f2fma(qqA[4], w4.x, aA); aB = f2fma(qqA[4], w4.y, aB);
                bA = f2fma(qqB[4], w4.x, bA); bB = f2fma(qqB[4], w4.y, bB);
                ulonglong2 w5 = *reinterpret_cast<const ulonglong2*>(sm + S_WO + 5*DD + d);
                aA = f2fma(qqA[5], w5.x, aA); aB = f2fma(qqA[5], w5.y, aB);
                bA = f2fma(qqB[5], w5.x, bA); bB = f2fma(qqB[5], w5.y, bB);
                ulonglong2 w6 = *reinterpret_cast<const ulonglong2*>(sm + S_WO + 6*DD + d);
                aA = f2fma(qqA[6], w6.x, aA); aB = f2fma(qqA[6], w6.y, aB);
                bA = f2fma(qqB[6], w6.x, bA); bB = f2fma(qqB[6], w6.y, bB);
                ulonglong2 w7 = *reinterpret_cast<const ulonglong2*>(sm + S_WO + 7*DD + d);
                aA = f2fma(qqA[7], w7.x, aA); aB = f2fma(qqA[7], w7.y, aB);
                bA = f2fma(qqB[7], w7.x, bA); bB = f2fma(qqB[7], w7.y, bB);
                ulonglong2 bo = *reinterpret_cast<const ulonglong2*>(sm + S_BOUT + d);
                aA = f2add(aA, bo.x); aB = f2add(aB, bo.y);
                bA = f2add(bA, bo.x); bB = f2add(bB, bo.y);
                float a0,a1,a2,a3;
                upk2(a0,a1,aA); upk2(a2,a3,aB);
                rA[dg*4    ] -= a0; rA[dg*4 + 1] -= a1;
                rA[dg*4 + 2] -= a2; rA[dg*4 + 3] -= a3;
                upk2(a0,a1,bA); upk2(a2,a3,bB);
                rB[dg*4    ] -= a0; rB[dg*4 + 1] -= a1;
                rB[dg*4 + 2] -= a2; rB[dg*4 + 3] -= a3;
            }
        }
    }

    // ---- epilogue: z_q = z - r_final (both positions, coalesced) ----
    {
        float* oqA = out + ZQ_OFF + ((size_t)(b * DD + d0)) * TT + t0 + pA;
        float* oqB = oqA + 32;
#pragma unroll
        for (int dd = 0; dd < 32; dd++) {
            oqA[(size_t)dd * TT] = zcA[(size_t)dd * TT] - rA[dd];
            oqB[(size_t)dd * TT] = zcB[(size_t)dd * TT] - rB[dd];
        }
    }

    // ---- loss: deterministic in-block sum, one atomic; last CTA writes scalars ----
    __syncthreads();
    double* lb = reinterpret_cast<double*>(sm + S_LOSS);
    if (tid < 64) lb[tid] = lossAcc;
    __syncthreads();
    if (tid == 0) {
        double s = 0.0;
        for (int j = 0; j < 64; j++) s += lb[j];
        atomicAdd(&g_loss, s);
        __threadfence();
        unsigned done = atomicAdd(&g_done, 1u);
        if (done == (unsigned)(gridDim.x - 1)) {
            double L = atomicAdd(&g_loss, 0.0);      // fenced read after all adds
            float v = (float)(L * (1.0 / 524288.0)); // / (B*CDIM*T)
            out[LOSS_OFF]     = v;   // commitment_loss
            out[LOSS_OFF + 1] = v;   // codebook_loss (identical in eval forward)
        }
    }
}

// ---------------- launch ----------------
extern "C" void kernel_launch(void* const* d_in, const int* in_sizes, int n_in,
                              void* d_out, int out_size) {
    const float* z     = (const float*)d_in[0];
    const float* w_in  = (const float*)d_in[1];
    const float* b_in  = (const float*)d_in[2];
    const float* w_out = (const float*)d_in[3];
    const float* b_out = (const float*)d_in[4];
    const float* cb    = (const float*)d_in[5];
    float* out = (float*)d_out;

    cudaFuncSetAttribute(rvq_main, cudaFuncAttributeMaxDynamicSharedMemorySize, SMEM_BYTES);

    rvq_prep<<<40, 256>>>(cb, w_in, w_out);
    rvq_main<<<NCTAS, THREADS, SMEM_BYTES>>>(z, b_in, b_out, cb, out);
}

// round 10
// speedup vs baseline: 1.3479x; 1.0883x over previous
#include <cuda_runtime.h>

// ---------------- problem constants ----------------
#define NCB   9
#define BB    16
#define DD    512
#define TT    4096
#define KK    1024
#define CDIM  8

#define TILE     64
#define THREADS  512
#define NCTAS    ((BB * TT) / TILE)     // 1024

// output layout (float32, concatenated)
#define ZQ_OFF     0ll
#define CODES_OFF  33554432ll
#define LAT_OFF    34144256ll
#define LOSS_OFF   38862848ll

// ---------------- smem layout (float offsets) ----------------
#define S_WI0   0          // w_in buf0 [d][c] 4096
#define S_WI1   4096       // w_in buf1 4096
#define S_WO    8192       // [c][d] 4096
#define S_CBT   12288      // [c][k] 8192
#define S_C2    20480      // 1024
#define S_CBR   21504      // RAW codebook [k][c] 8192
#define S_BOUT  29696      // 512
#define S_BIN   30208      // 8
#define S_ZE    30216      // [c][p] 512
#define S_EN    30728      // [c][p] 512
#define S_EN2   31240      // 64
#define S_PART  31304      // 64*129 = 8256 (A partials; reused for BESTD/BESTI)
#define S_BESTD S_PART                   // 16*64 = 1024
#define S_BESTI (S_PART+1024)            // 1024 ints
#define S_CBQ   39560      // [p*9+c] 576
#define S_LOSS  40136      // 64 doubles = 128 floats (byte 160544, 8-aligned)
#define SMEM_FLOATS 40264
#define SMEM_BYTES  (SMEM_FLOATS*4)   // 161056

// ---------------- device scratch ----------------
__device__ float    g_wi_p[NCB * DD * CDIM];   // [i][d][c]
__device__ float    g_wo_t[NCB * CDIM * DD];   // [i][c][d]
__device__ float    g_cbt [NCB * CDIM * KK];   // [i][c][k] (normalized, transposed)
__device__ float    g_c2  [NCB * KK];
__device__ double   g_loss;
__device__ unsigned g_done;

// ---------------- packed f32x2 helpers ----------------
typedef unsigned long long u64;
__device__ __forceinline__ u64 pk2(float lo, float hi) {
    u64 r; asm("mov.b64 %0,{%1,%2};" : "=l"(r) : "f"(lo), "f"(hi)); return r;
}
__device__ __forceinline__ void upk2(float& lo, float& hi, u64 v) {
    asm("mov.b64 {%0,%1},%2;" : "=f"(lo), "=f"(hi) : "l"(v));
}
__device__ __forceinline__ u64 f2fma(u64 a, u64 b, u64 c) {
    u64 d; asm("fma.rn.f32x2 %0,%1,%2,%3;" : "=l"(d) : "l"(a), "l"(b), "l"(c)); return d;
}
__device__ __forceinline__ u64 f2mul(u64 a, u64 b) {
    u64 d; asm("mul.rn.f32x2 %0,%1,%2;" : "=l"(d) : "l"(a), "l"(b)); return d;
}
__device__ __forceinline__ u64 f2add(u64 a, u64 b) {
    u64 d; asm("add.rn.f32x2 %0,%1,%2;" : "=l"(d) : "l"(a), "l"(b)); return d;
}
__device__ __forceinline__ void cp16(unsigned smaddr, const float* g) {
    asm volatile("cp.async.cg.shared.global [%0], [%1], 16;" :: "r"(smaddr), "l"(g));
}
#define CP_COMMIT() asm volatile("cp.async.commit_group;")
#define CP_WAIT(n)  asm volatile("cp.async.wait_group %0;" :: "n"(n))

// ---------------- prep: normalize + transpose, zero loss ----------------
__global__ void rvq_prep(const float* __restrict__ cb,
                         const float* __restrict__ w_in,
                         const float* __restrict__ w_out) {
    int v = blockIdx.x * blockDim.x + threadIdx.x;
    if (v == 0) { g_loss = 0.0; g_done = 0u; }
    if (v < NCB * KK) {
        int i = v / KK, k = v % KK;
        const float* src = cb + (size_t)v * CDIM;
        float x[CDIM];
#pragma unroll
        for (int c = 0; c < CDIM; c++) x[c] = src[c];
        float ss = 0.f;
#pragma unroll
        for (int c = 0; c < CDIM; c++) ss = fmaf(x[c], x[c], ss);
        float den = fmaxf(__fsqrt_rn(ss), 1e-12f);
        float c2 = 0.f;
#pragma unroll
        for (int c = 0; c < CDIM; c++) {
            float e = __fdiv_rn(x[c], den);   // exact IEEE div, matches reference
            g_cbt[((size_t)i * CDIM + c) * KK + k] = e;
            c2 = fmaf(e, e, c2);
        }
        g_c2[v] = c2;
    }
    for (int idx = v; idx < NCB * DD * CDIM; idx += gridDim.x * blockDim.x) {
        int i = idx / (DD * CDIM), rem = idx % (DD * CDIM);
        int c = rem / DD, d = rem % DD;
        g_wi_p[(size_t)i * DD * CDIM + d * CDIM + c] = w_in[idx];       // idx=[i][c][d]
        int d2 = rem / CDIM, c2i = rem % CDIM;
        g_wo_t[(size_t)i * CDIM * DD + c2i * DD + d2] = w_out[idx];     // idx=[i][d][c]
    }
}

// ---------------- main fused kernel ----------------
extern __shared__ float sm[];

__global__ void __launch_bounds__(THREADS, 1)
rvq_main(const float* __restrict__ z,
         const float* __restrict__ b_in,
         const float* __restrict__ b_out,
         const float* __restrict__ cbraw,
         float* __restrict__ out) {
    const int tid  = threadIdx.x;
    const int pos0 = blockIdx.x * TILE;
    const int b    = pos0 >> 12;
    const int t0   = pos0 & (TT - 1);
    const unsigned smb = (unsigned)__cvta_generic_to_shared(sm);

    // A/C mapping: 2 positions (pA, pA+32) x 32-dim chunk
    const int pA = tid & 31;
    const int ch = tid >> 5;          // 0..15
    const int d0 = ch << 5;

    // B mapping: 16 k-slices x 32 position-pairs
    const int pb  = pA;
    const int slb = ch;

    // latents/ZE mapping
    const int p64 = tid & 63;
    const int sl8 = tid >> 6;

    // residual in REGISTERS
    const float* zcA = z + ((size_t)b * DD + d0) * TT + t0 + pA;
    const float* zcB = zcA + 32;
    float rA[32], rB[32];
#pragma unroll
    for (int dd = 0; dd < 32; dd++) { rA[dd] = zcA[(size_t)dd * TT]; rB[dd] = zcB[(size_t)dd * TT]; }

    double lossAcc = 0.0;

    // preload w_in for codebook 0 into buf0
    cp16(smb + (S_WI0 + tid * 4) * 4,        g_wi_p + tid * 4);
    cp16(smb + (S_WI0 + 2048 + tid * 4) * 4, g_wi_p + 2048 + tid * 4);
    CP_COMMIT();

    for (int i = 0; i < NCB; ++i) {
        __syncthreads();   // prev iter's C done before restage

        // ---- G1: cbt + c2 + raw codebook + b_in ----
        {
            const float* ct = g_cbt + (size_t)i * CDIM * KK;
#pragma unroll
            for (int r4 = 0; r4 < 4; r4++)
                cp16(smb + (S_CBT + r4 * 2048 + tid * 4) * 4, ct + r4 * 2048 + tid * 4);
            if (tid < 256) cp16(smb + (S_C2 + tid * 4) * 4, g_c2 + (size_t)i * KK + tid * 4);
            const float* cr = cbraw + (size_t)i * KK * CDIM;
#pragma unroll
            for (int r4 = 0; r4 < 4; r4++)
                cp16(smb + (S_CBR + r4 * 2048 + tid * 4) * 4, cr + r4 * 2048 + tid * 4);
            if (tid < 2) cp16(smb + (S_BIN + tid * 4) * 4, b_in + (size_t)i * CDIM + tid * 4);
        }
        CP_COMMIT();
        // ---- G2: wo + bout ----
        {
            const float* wo = g_wo_t + (size_t)i * CDIM * DD;
            cp16(smb + (S_WO + tid * 4) * 4,        wo + tid * 4);
            cp16(smb + (S_WO + 2048 + tid * 4) * 4, wo + 2048 + tid * 4);
            if (tid < 128) cp16(smb + (S_BOUT + tid * 4) * 4, b_out + (size_t)i * DD + tid * 4);
        }
        CP_COMMIT();
        // ---- G3: prefetch NEXT codebook's w_in into the other buffer ----
        {
            const int inx = (i < NCB - 1) ? i + 1 : i;     // clamp (harmless reload)
            const int nb  = S_WI0 + ((i + 1) & 1) * 4096;
            const float* wi = g_wi_p + (size_t)inx * DD * CDIM;
            cp16(smb + (nb + tid * 4) * 4,        wi + tid * 4);
            cp16(smb + (nb + 2048 + tid * 4) * 4, wi + 2048 + tid * 4);
        }
        CP_COMMIT();

        CP_WAIT(3);    // current w_in (committed last iter / preloop) ready
        __syncthreads();

        const int wiB = S_WI0 + (i & 1) * 4096;

        // ---- Phase A: partials for 2 positions over 32-dim chunk ----
        {
            u64 aP01=0, aP23=0, aP45=0, aP67=0;
            u64 aQ01=0, aQ23=0, aQ45=0, aQ67=0;
#pragma unroll
            for (int dd = 0; dd < 32; dd++) {
                ulonglong2 wA = *reinterpret_cast<const ulonglong2*>(sm + wiB + (d0 + dd) * 8);
                ulonglong2 wB = *reinterpret_cast<const ulonglong2*>(sm + wiB + (d0 + dd) * 8 + 4);
                u64 rP = pk2(rA[dd], rA[dd]);
                u64 rQ = pk2(rB[dd], rB[dd]);
                aP01 = f2fma(wA.x, rP, aP01); aQ01 = f2fma(wA.x, rQ, aQ01);
                aP23 = f2fma(wA.y, rP, aP23); aQ23 = f2fma(wA.y, rQ, aQ23);
                aP45 = f2fma(wB.x, rP, aP45); aQ45 = f2fma(wB.x, rQ, aQ45);
                aP67 = f2fma(wB.y, rP, aP67); aQ67 = f2fma(wB.y, rQ, aQ67);
            }
            float v0,v1,v2,v3,v4,v5,v6,v7;
            float* pbA = sm + S_PART + pA * 129 + ch;          // [p][c*16+ch]
            upk2(v0,v1,aP01); upk2(v2,v3,aP23); upk2(v4,v5,aP45); upk2(v6,v7,aP67);
            pbA[0]=v0;  pbA[16]=v1; pbA[32]=v2; pbA[48]=v3;
            pbA[64]=v4; pbA[80]=v5; pbA[96]=v6; pbA[112]=v7;
            float* pbB = sm + S_PART + (pA + 32) * 129 + ch;
            upk2(v0,v1,aQ01); upk2(v2,v3,aQ23); upk2(v4,v5,aQ45); upk2(v6,v7,aQ67);
            pbB[0]=v0;  pbB[16]=v1; pbB[32]=v2; pbB[48]=v3;
            pbB[64]=v4; pbB[80]=v5; pbB[96]=v6; pbB[112]=v7;
        }
        CP_WAIT(2);   // cbt + c2 + cbr + bin ready (G2, G3 may pend)
        __syncthreads();

        // ---- combineA + normalize (tid<64): z_e, en, en2 ----
        if (tid < 64) {
            float zv[8];
#pragma unroll
            for (int c = 0; c < 8; c++) {
                const float* pbuf = sm + S_PART + tid * 129 + c * 16;
                float s = pbuf[0];
#pragma unroll
                for (int j = 1; j < 16; j++) s += pbuf[j];   // ascending dim-chunk order
                zv[c] = s + sm[S_BIN + c];
                sm[S_ZE + c * 64 + tid] = zv[c];
            }
            float ss = 0.f;
#pragma unroll
            for (int c = 0; c < 8; c++) ss = fmaf(zv[c], zv[c], ss);
            float den = fmaxf(__fsqrt_rn(ss), 1e-12f);
            float e[8], en2 = 0.f;
#pragma unroll
            for (int c = 0; c < 8; c++) { e[c] = __fdiv_rn(zv[c], den); sm[S_EN + c * 64 + tid] = e[c]; }
#pragma unroll
            for (int c = 0; c < 8; c++) en2 = fmaf(e[c], e[c], en2);
            sm[S_EN2 + tid] = en2;
        }
        __syncthreads();

        // ---- Phase B: 2 positions per thread, 64 codes per slice ----
        {
            u64 eP[8], eQ[8];
#pragma unroll
            for (int c = 0; c < 8; c++) {
                float ep = sm[S_EN + c * 64 + pb];
                float eq = sm[S_EN + c * 64 + pb + 32];
                eP[c] = pk2(ep, ep);
                eQ[c] = pk2(eq, eq);
            }
            float en2P = sm[S_EN2 + pb];
            float en2Q = sm[S_EN2 + pb + 32];
            u64 e2sP = pk2(en2P, en2P);
            u64 e2sQ = pk2(en2Q, en2Q);
            u64 m2s  = pk2(-2.f, -2.f);

            const int k0 = slb << 6;
            float bPx = 3.402823466e38f, bPy = bPx, bQx = bPx, bQy = bPx;
            int   iPx = k0, iPy = k0, iQx = k0, iQy = k0;
#pragma unroll 4
            for (int q = 0; q < 16; ++q) {
                const int kb = k0 + (q << 2);
                ulonglong2 c0 = *reinterpret_cast<const ulonglong2*>(sm + S_CBT + 0*KK + kb);
                ulonglong2 c1 = *reinterpret_cast<const ulonglong2*>(sm + S_CBT + 1*KK + kb);
                ulonglong2 c2r= *reinterpret_cast<const ulonglong2*>(sm + S_CBT + 2*KK + kb);
                ulonglong2 c3 = *reinterpret_cast<const ulonglong2*>(sm + S_CBT + 3*KK + kb);
                ulonglong2 c4 = *reinterpret_cast<const ulonglong2*>(sm + S_CBT + 4*KK + kb);
                ulonglong2 c5 = *reinterpret_cast<const ulonglong2*>(sm + S_CBT + 5*KK + kb);
                ulonglong2 c6 = *reinterpret_cast<const ulonglong2*>(sm + S_CBT + 6*KK + kb);
                ulonglong2 c7 = *reinterpret_cast<const ulonglong2*>(sm + S_CBT + 7*KK + kb);
                ulonglong2 c2p = *reinterpret_cast<const ulonglong2*>(sm + S_C2 + kb);

                u64 dAP = f2mul(eP[0], c0.x);
                dAP = f2fma(eP[1], c1.x, dAP); dAP = f2fma(eP[2], c2r.x, dAP);
                dAP = f2fma(eP[3], c3.x, dAP); dAP = f2fma(eP[4], c4.x, dAP);
                dAP = f2fma(eP[5], c5.x, dAP); dAP = f2fma(eP[6], c6.x, dAP);
                dAP = f2fma(eP[7], c7.x, dAP);
                u64 dBP = f2mul(eP[0], c0.y);
                dBP = f2fma(eP[1], c1.y, dBP); dBP = f2fma(eP[2], c2r.y, dBP);
                dBP = f2fma(eP[3], c3.y, dBP); dBP = f2fma(eP[4], c4.y, dBP);
                dBP = f2fma(eP[5], c5.y, dBP); dBP = f2fma(eP[6], c6.y, dBP);
                dBP = f2fma(eP[7], c7.y, dBP);
                u64 dAQ = f2mul(eQ[0], c0.x);
                dAQ = f2fma(eQ[1], c1.x, dAQ); dAQ = f2fma(eQ[2], c2r.x, dAQ);
                dAQ = f2fma(eQ[3], c3.x, dAQ); dAQ = f2fma(eQ[4], c4.x, dAQ);
                dAQ = f2fma(eQ[5], c5.x, dAQ); dAQ = f2fma(eQ[6], c6.x, dAQ);
                dAQ = f2fma(eQ[7], c7.x, dAQ);
                u64 dBQ = f2mul(eQ[0], c0.y);
                dBQ = f2fma(eQ[1], c1.y, dBQ); dBQ = f2fma(eQ[2], c2r.y, dBQ);
                dBQ = f2fma(eQ[3], c3.y, dBQ); dBQ = f2fma(eQ[4], c4.y, dBQ);
                dBQ = f2fma(eQ[5], c5.y, dBQ); dBQ = f2fma(eQ[6], c6.y, dBQ);
                dBQ = f2fma(eQ[7], c7.y, dBQ);

                u64 sAP = f2add(f2fma(m2s, dAP, e2sP), c2p.x);   // (en2-2dot)+c2, per-lane exact
                u64 sBP = f2add(f2fma(m2s, dBP, e2sP), c2p.y);
                u64 sAQ = f2add(f2fma(m2s, dAQ, e2sQ), c2p.x);
                u64 sBQ = f2add(f2fma(m2s, dBQ, e2sQ), c2p.y);

                float f0,f1,f2,f3;
                upk2(f0,f1,sAP); upk2(f2,f3,sBP);
                if (f0 < bPx) { bPx = f0; iPx = kb;     }   // strict <: chain keeps lowest q
                if (f1 < bPx) { bPx = f1; iPx = kb + 1; }
                if (f2 < bPy) { bPy = f2; iPy = kb + 2; }
                if (f3 < bPy) { bPy = f3; iPy = kb + 3; }
                upk2(f0,f1,sAQ); upk2(f2,f3,sBQ);
                if (f0 < bQx) { bQx = f0; iQx = kb;     }
                if (f1 < bQx) { bQx = f1; iQx = kb + 1; }
                if (f2 < bQy) { bQy = f2; iQy = kb + 2; }
                if (f3 < bQy) { bQy = f3; iQy = kb + 3; }
            }
            // merge chains with exact lowest-index tie-break
            float bP = bPx; int iP = iPx;
            if (bPy < bP || (bPy == bP && iPy < iP)) { bP = bPy; iP = iPy; }
            float bQ = bQx; int iQ = iQx;
            if (bQy < bQ || (bQy == bQ && iQy < iQ)) { bQ = bQy; iQ = iQy; }
            sm[S_BESTD + (slb << 6) + pb]      = bP;
            sm[S_BESTD + (slb << 6) + pb + 32] = bQ;
            reinterpret_cast<int*>(sm + S_BESTI)[(slb << 6) + pb]      = iP;
            reinterpret_cast<int*>(sm + S_BESTI)[(slb << 6) + pb + 32] = iQ;
        }
        __syncthreads();

        // ---- combineB: latents, codes, gather raw codebook (smem), loss ----
        out[LAT_OFF + ((size_t)(b * (NCB*CDIM) + i*CDIM + sl8)) * TT + t0 + p64] =
            sm[S_ZE + sl8 * 64 + p64];
        if (tid < 64) {
            float bestd = sm[S_BESTD + tid];
            int   bi    = reinterpret_cast<int*>(sm + S_BESTI)[tid];
#pragma unroll
            for (int s = 1; s < 16; s++) {    // ascending k ranges: strict < keeps lowest k
                float d2 = sm[S_BESTD + (s << 6) + tid];
                int   i2 = reinterpret_cast<int*>(sm + S_BESTI)[(s << 6) + tid];
                if (d2 < bestd) { bestd = d2; bi = i2; }
            }
            out[CODES_OFF + ((size_t)(b * NCB + i)) * TT + t0 + tid] = (float)bi;
            // raw codebook row from SMEM (no global gather latency)
            float4 cA = *reinterpret_cast<const float4*>(sm + S_CBR + bi * 8);
            float4 cB = *reinterpret_cast<const float4*>(sm + S_CBR + bi * 8 + 4);
            float cv[8] = {cA.x, cA.y, cA.z, cA.w, cB.x, cB.y, cB.z, cB.w};
            float dsq[8];
#pragma unroll
            for (int cc = 0; cc < 8; cc++) {
                sm[S_CBQ + tid * 9 + cc] = cv[cc];
                float df = sm[S_ZE + cc * 64 + tid] - cv[cc];
                dsq[cc] = df * df;
            }
            // short float tree + single double add (reference squares in fp32 too)
            float fs = ((dsq[0] + dsq[1]) + (dsq[2] + dsq[3]))
                     + ((dsq[4] + dsq[5]) + (dsq[6] + dsq[7]));
            lossAcc += (double)fs;
        }
        CP_WAIT(1);   // wo + bout ready (next-wi may pend)
        __syncthreads();

        // ---- Phase C: both positions' residuals updated with shared w loads ----
        {
            u64 qqA[8], qqB[8];
#pragma unroll
            for (int c = 0; c < 8; c++) {
                float qa = sm[S_CBQ + pA * 9 + c];
                float qb = sm[S_CBQ + (pA + 32) * 9 + c];
                qqA[c] = pk2(qa, qa);
                qqB[c] = pk2(qb, qb);
            }
#pragma unroll
            for (int dg = 0; dg < 8; dg++) {
                const int d = d0 + dg * 4;
                ulonglong2 w0 = *reinterpret_cast<const ulonglong2*>(sm + S_WO + 0*DD + d);
                u64 aA = f2mul(qqA[0], w0.x);
                u64 aB = f2mul(qqA[0], w0.y);
                u64 bA = f2mul(qqB[0], w0.x);
                u64 bB = f2mul(qqB[0], w0.y);
                ulonglong2 w1 = *reinterpret_cast<const ulonglong2*>(sm + S_WO + 1*DD + d);
                aA = f2fma(qqA[1], w1.x, aA); aB = f2fma(qqA[1], w1.y, aB);
                bA = f2fma(qqB[1], w1.x, bA); bB = f2fma(qqB[1], w1.y, bB);
                ulonglong2 w2 = *reinterpret_cast<const ulonglong2*>(sm + S_WO + 2*DD + d);
                aA = f2fma(qqA[2], w2.x, aA); aB = f2fma(qqA[2], w2.y, aB);
                bA = f2fma(qqB[2], w2.x, bA); bB = f2fma(qqB[2], w2.y, bB);
                ulonglong2 w3 = *reinterpret_cast<const ulonglong2*>(sm + S_WO + 3*DD + d);
                aA = f2fma(qqA[3], w3.x, aA); aB = f2fma(qqA[3], w3.y, aB);
                bA = f2fma(qqB[3], w3.x, bA); bB = f2fma(qqB[3], w3.y, bB);
                ulonglong2 w4 = *reinterpret_cast<const ulonglong2*>(sm + S_WO + 4*DD + d);
                aA = f2fma(qqA[4], w4.x, aA); aB = f2fma(qqA[4], w4.y, aB);
                bA = f2fma(qqB[4], w4.x, bA); bB = f2fma(qqB[4], w4.y, bB);
                ulonglong2 w5 = *reinterpret_cast<const ulonglong2*>(sm + S_WO + 5*DD + d);
                aA = f2fma(qqA[5], w5.x, aA); aB = f2fma(qqA[5], w5.y, aB);
                bA = f2fma(qqB[5], w5.x, bA); bB = f2fma(qqB[5], w5.y, bB);
                ulonglong2 w6 = *reinterpret_cast<const ulonglong2*>(sm + S_WO + 6*DD + d);
                aA = f2fma(qqA[6], w6.x, aA); aB = f2fma(qqA[6], w6.y, aB);
                bA = f2fma(qqB[6], w6.x, bA); bB = f2fma(qqB[6], w6.y, bB);
                ulonglong2 w7 = *reinterpret_cast<const ulonglong2*>(sm + S_WO + 7*DD + d);
                aA = f2fma(qqA[7], w7.x, aA); aB = f2fma(qqA[7], w7.y, aB);
                bA = f2fma(qqB[7], w7.x, bA); bB = f2fma(qqB[7], w7.y, bB);
                ulonglong2 bo = *reinterpret_cast<const ulonglong2*>(sm + S_BOUT + d);
                aA = f2add(aA, bo.x); aB = f2add(aB, bo.y);
                bA = f2add(bA, bo.x); bB = f2add(bB, bo.y);
                float a0,a1,a2,a3;
                upk2(a0,a1,aA); upk2(a2,a3,aB);
                rA[dg*4    ] -= a0; rA[dg*4 + 1] -= a1;
                rA[dg*4 + 2] -= a2; rA[dg*4 + 3] -= a3;
                upk2(a0,a1,bA); upk2(a2,a3,bB);
                rB[dg*4    ] -= a0; rB[dg*4 + 1] -= a1;
                rB[dg*4 + 2] -= a2; rB[dg*4 + 3] -= a3;
            }
        }
    }

    // ---- epilogue: z_q = z - r_final (both positions, coalesced) ----
    {
        float* oqA = out + ZQ_OFF + ((size_t)(b * DD + d0)) * TT + t0 + pA;
        float* oqB = oqA + 32;
#pragma unroll
        for (int dd = 0; dd < 32; dd++) {
            oqA[(size_t)dd * TT] = zcA[(size_t)dd * TT] - rA[dd];
            oqB[(size_t)dd * TT] = zcB[(size_t)dd * TT] - rB[dd];
        }
    }

    // ---- loss: deterministic in-block sum, one atomic; last CTA writes scalars ----
    __syncthreads();
    double* lb = reinterpret_cast<double*>(sm + S_LOSS);
    if (tid < 64) lb[tid] = lossAcc;
    __syncthreads();
    if (tid == 0) {
        double s = 0.0;
        for (int j = 0; j < 64; j++) s += lb[j];
        atomicAdd(&g_loss, s);
        __threadfence();
        unsigned done = atomicAdd(&g_done, 1u);
        if (done == (unsigned)(gridDim.x - 1)) {
            double L = atomicAdd(&g_loss, 0.0);      // fenced read after all adds
            float v = (float)(L * (1.0 / 524288.0)); // / (B*CDIM*T)
            out[LOSS_OFF]     = v;   // commitment_loss
            out[LOSS_OFF + 1] = v;   // codebook_loss (identical in eval forward)
        }
    }
}

// ---------------- launch ----------------
extern "C" void kernel_launch(void* const* d_in, const int* in_sizes, int n_in,
                              void* d_out, int out_size) {
    const float* z     = (const float*)d_in[0];
    const float* w_in  = (const float*)d_in[1];
    const float* b_in  = (const float*)d_in[2];
    const float* w_out = (const float*)d_in[3];
    const float* b_out = (const float*)d_in[4];
    const float* cb    = (const float*)d_in[5];
    float* out = (float*)d_out;

    cudaFuncSetAttribute(rvq_main, cudaFuncAttributeMaxDynamicSharedMemorySize, SMEM_BYTES);

    rvq_prep<<<40, 256>>>(cb, w_in, w_out);
    rvq_main<<<NCTAS, THREADS, SMEM_BYTES>>>(z, b_in, b_out, cb, out);
}